// round 14
// baseline (speedup 1.0000x reference)
#include <cuda_runtime.h>
#include <cuda_fp16.h>
#include <cstdint>

#define NN 40000
#define NE 640000
#define TILE 96
#define NTH 256
#define NBLK ((NE + TILE - 1) / TILE)   // 6667 (last tile: 64 edges)
#define SA 392   // A-plane smem stride (halves): 784 B -> %128==16, conflict-free
#define SW 136   // W-plane smem stride (halves): 272 B -> %128==16, conflict-free

typedef unsigned int u32;

// ---- device scratch ----
__device__ __half g_e1h[(size_t)NE * 128];   // ea-split before phase A, e1-split after
__device__ __half g_e1l[(size_t)NE * 128];
__device__ float  g_x1[(size_t)NN * 128];
__device__ __half g_xh[(size_t)NN * 128];
__device__ __half g_xl[(size_t)NN * 128];
__device__ __half g_x1h[(size_t)NN * 128];
__device__ __half g_x1l[(size_t)NN * 128];
__device__ __half g_x2h[(size_t)NN * 128];
__device__ __half g_x2l[(size_t)NN * 128];
__device__ __half g_w[229376];               // single fp16 plane, transposed [n][k]

#define W_E1W1 0
#define W_E1W2 49152
#define W_N1W1 65536
#define W_N1W2 98304
#define W_N2W1 114688
#define W_N2W2 147456
#define W_E2W1 163840
#define W_E2W2 212992

struct SM {
    __half Ah[TILE * SA];     // 75264 B ; per-row bytes [0,512) double as fp32 staging
    __half Al[TILE * SA];     // 75264 B
    __half W[2][128 * SW];    // 2 x 34816 B (double buffer, 128-k chunks)
    float b1[128];
    float b2[128];
    int rowI[TILE];
    int colI[TILE];
};                            // ~217 KB

// ---- helpers ----
__device__ __forceinline__ u32 cvta(const void* p) {
    return (u32)__cvta_generic_to_shared(p);
}
__device__ __forceinline__ void cpasync16(u32 dst, const void* src) {
    asm volatile("cp.async.cg.shared.global [%0], [%1], 16;" :: "r"(dst), "l"(src) : "memory");
}
__device__ __forceinline__ void cp_commit() {
    asm volatile("cp.async.commit_group;" ::: "memory");
}
__device__ __forceinline__ void cp_wait0() {
    asm volatile("cp.async.wait_group 0;" ::: "memory");
}
__device__ __forceinline__ void cp_wait1() {
    asm volatile("cp.async.wait_group 1;" ::: "memory");
}
__device__ __forceinline__ void ldsm4(u32 addr, u32& r0, u32& r1, u32& r2, u32& r3) {
    asm volatile("ldmatrix.sync.aligned.m8n8.x4.shared.b16 {%0,%1,%2,%3}, [%4];"
                 : "=r"(r0), "=r"(r1), "=r"(r2), "=r"(r3) : "r"(addr));
}
__device__ __forceinline__ void mma16816(float* c, const u32* a, const u32* b) {
    asm volatile("mma.sync.aligned.m16n8k16.row.col.f32.f16.f16.f32 "
                 "{%0,%1,%2,%3}, {%4,%5,%6,%7}, {%8,%9}, {%0,%1,%2,%3};"
                 : "+f"(c[0]), "+f"(c[1]), "+f"(c[2]), "+f"(c[3])
                 : "r"(a[0]), "r"(a[1]), "r"(a[2]), "r"(a[3]), "r"(b[0]), "r"(b[1]));
}
__device__ __forceinline__ void red4(float* p, float4 v) {
    asm volatile("red.global.add.v4.f32 [%0], {%1,%2,%3,%4};"
                 :: "l"(p), "f"(v.x), "f"(v.y), "f"(v.z), "f"(v.w) : "memory");
}
__device__ __forceinline__ void split2(float x, __half& h, __half& l) {
    h = __float2half_rn(x);
    l = __float2half_rn(x - __half2float(h));
}
__device__ __forceinline__ void store_h2(__half* ph, __half* pl, float x0, float x1) {
    __half h0,l0,h1,l1; split2(x0,h0,l0); split2(x1,h1,l1);
    __half2 t;
    t.x=h0; t.y=h1; *(__half2*)ph = t;
    t.x=l0; t.y=l1; *(__half2*)pl = t;
}

// block-wide staging of one 128-k chunk (single fp16 plane, 32 KB)
__device__ __forceinline__ void stage_w(SM* sm, int buf,
    const __half* __restrict__ gw, int K, int k0)
{
    u32 d = cvta(&sm->W[buf][0]);
    for (int i = threadIdx.x; i < 2048; i += NTH) {
        int r = i >> 4, s = (i & 15) << 3;
        cpasync16(d + (u32)((r * SW + s) * 2), gw + (size_t)r * K + k0 + s);
    }
}

// GEMM (2-plane A): C[96 x 128] += (Ah+Al) x W^T. 8 warps, warp tile 48x32.
// 128-k chunks. Caller staged+committed chunk0 into buf startBuf.
// firstWait=1: allow ONE trailing pending group at chunk0 (prologue G2).
__device__ __forceinline__ void run_gemm(SM* sm, int aCol, int K,
    const __half* __restrict__ gw, float C[3][4][4], int firstWait, int startBuf)
{
    const int tid = threadIdx.x, lane = tid & 31, wid = tid >> 5;
    const int wM = wid >> 2, wN = wid & 3;
#pragma unroll
    for (int i = 0; i < 3; i++)
#pragma unroll
        for (int j = 0; j < 4; j++)
#pragma unroll
            for (int q = 0; q < 4; q++) C[i][j][q] = 0.f;

    const u32 ah_base = cvta(sm->Ah), al_base = cvta(sm->Al);
    const u32 w_base[2] = { cvta(&sm->W[0][0]), cvta(&sm->W[1][0]) };

    const int aRow0 = wM * 48 + (lane & 15);
    const int aColL = (lane >> 4) * 8;
    const int bRowL = (lane & 7) + ((lane & 16) >> 1);
    const int bColL = lane & 8;

    const int nchunk = K >> 7;
    for (int c = 0; c < nchunk; c++) {
        if (c == 0 && firstWait) cp_wait1(); else cp_wait0();
        __syncthreads();
        if (c + 1 < nchunk) {
            stage_w(sm, (startBuf + c + 1) & 1, gw, K, (c + 1) << 7);
            cp_commit();
        }
        const int buf = (startBuf + c) & 1, k0 = c << 7;
#pragma unroll
        for (int kk = 0; kk < 128; kk += 16) {
            u32 a_h[3][4], a_l[3][4];
#pragma unroll
            for (int mi = 0; mi < 3; mi++) {
                u32 off = (u32)(((aRow0 + mi * 16) * SA + aCol + k0 + kk + aColL) * 2);
                ldsm4(ah_base + off, a_h[mi][0], a_h[mi][1], a_h[mi][2], a_h[mi][3]);
                ldsm4(al_base + off, a_l[mi][0], a_l[mi][1], a_l[mi][2], a_l[mi][3]);
            }
            u32 b[4][2];
#pragma unroll
            for (int pr = 0; pr < 2; pr++) {
                u32 off = (u32)(((wN * 32 + pr * 16 + bRowL) * SW + kk + bColL) * 2);
                ldsm4(w_base[buf] + off, b[2*pr][0], b[2*pr][1], b[2*pr+1][0], b[2*pr+1][1]);
            }
#pragma unroll
            for (int mi = 0; mi < 3; mi++)
#pragma unroll
                for (int nb = 0; nb < 4; nb++) {
                    mma16816(C[mi][nb], a_h[mi], b[nb]);
                    mma16816(C[mi][nb], a_l[mi], b[nb]);
                }
        }
    }
}

// GEMM (1-plane A, fp16 hidden): C += Ah x W^T. K=128, single chunk in buf `wbuf`
// (caller staged+committed). Single barrier, no mid-GEMM syncs.
__device__ __forceinline__ void run_gemm_1p(SM* sm, int aCol,
    float C[3][4][4], int wbuf)
{
    const int tid = threadIdx.x, lane = tid & 31, wid = tid >> 5;
    const int wM = wid >> 2, wN = wid & 3;
#pragma unroll
    for (int i = 0; i < 3; i++)
#pragma unroll
        for (int j = 0; j < 4; j++)
#pragma unroll
            for (int q = 0; q < 4; q++) C[i][j][q] = 0.f;

    const u32 ah_base = cvta(sm->Ah);
    const u32 w_base = cvta(&sm->W[wbuf][0]);

    const int aRow0 = wM * 48 + (lane & 15);
    const int aColL = (lane >> 4) * 8;
    const int bRowL = (lane & 7) + ((lane & 16) >> 1);
    const int bColL = lane & 8;

    cp_wait0();
    __syncthreads();      // W ready + hidden writes visible
#pragma unroll
    for (int kk = 0; kk < 128; kk += 16) {
        u32 a_h[3][4];
#pragma unroll
        for (int mi = 0; mi < 3; mi++) {
            u32 off = (u32)(((aRow0 + mi * 16) * SA + aCol + kk + aColL) * 2);
            ldsm4(ah_base + off, a_h[mi][0], a_h[mi][1], a_h[mi][2], a_h[mi][3]);
        }
        u32 b[4][2];
#pragma unroll
        for (int pr = 0; pr < 2; pr++) {
            u32 off = (u32)(((wN * 32 + pr * 16 + bRowL) * SW + kk + bColL) * 2);
            ldsm4(w_base + off, b[2*pr][0], b[2*pr][1], b[2*pr+1][0], b[2*pr+1][1]);
        }
#pragma unroll
        for (int mi = 0; mi < 3; mi++)
#pragma unroll
            for (int nb = 0; nb < 4; nb++)
                mma16816(C[mi][nb], a_h[mi], b[nb]);
    }
}

// fragment owner: rows r=wM*48+mi*16+(lane>>2), r+8 ; cols c=wN*32+nb*8+(lane&3)*2
// hidden = relu(C+b1) as single fp16 plane -> Ah cols [256,384)
__device__ __forceinline__ void hidden_epilogue(SM* sm, float C[3][4][4]) {
    const int lane = threadIdx.x & 31, wid = threadIdx.x >> 5;
    const int wM = wid >> 2, wN = wid & 3, g = lane >> 2, q = (lane & 3) * 2;
#pragma unroll
    for (int mi = 0; mi < 3; mi++)
#pragma unroll
        for (int nb = 0; nb < 4; nb++) {
            int r = wM * 48 + mi * 16 + g, c = wN * 32 + nb * 8 + q;
            float b0 = sm->b1[c], b1v = sm->b1[c + 1];
            __half2 t0, t1;
            t0.x = __float2half_rn(fmaxf(C[mi][nb][0] + b0, 0.f));
            t0.y = __float2half_rn(fmaxf(C[mi][nb][1] + b1v, 0.f));
            t1.x = __float2half_rn(fmaxf(C[mi][nb][2] + b0, 0.f));
            t1.y = __float2half_rn(fmaxf(C[mi][nb][3] + b1v, 0.f));
            *(__half2*)&sm->Ah[r * SA + 256 + c] = t0;
            *(__half2*)&sm->Ah[(r + 8) * SA + 256 + c] = t1;
        }
}

// stage C (+bias) as fp32 into Ah per-row bytes [0,512) — disjoint from the last
// GEMM's A reads at half-cols [256,384) = bytes [512,768).
__device__ __forceinline__ void stage_c_f32(SM* sm, float C[3][4][4]) {
    const int lane = threadIdx.x & 31, wid = threadIdx.x >> 5;
    const int wM = wid >> 2, wN = wid & 3, g = lane >> 2, q = (lane & 3) * 2;
#pragma unroll
    for (int mi = 0; mi < 3; mi++)
#pragma unroll
        for (int nb = 0; nb < 4; nb++) {
            int r = wM * 48 + mi * 16 + g, c = wN * 32 + nb * 8 + q;
            float b0 = sm->b2[c], b1v = sm->b2[c + 1];
            float* p0 = (float*)((char*)sm->Ah + (size_t)r * (SA * 2));
            float* p1 = (float*)((char*)sm->Ah + (size_t)(r + 8) * (SA * 2));
            *(float2*)&p0[c] = make_float2(C[mi][nb][0] + b0, C[mi][nb][1] + b1v);
            *(float2*)&p1[c] = make_float2(C[mi][nb][2] + b0, C[mi][nb][3] + b1v);
        }
}

// v4 scatter from the fp32 staging region
__device__ __forceinline__ void scatter_v4(SM* sm, float C[3][4][4],
                                           float* __restrict__ dst, int rem)
{
    stage_c_f32(sm, C);
    __syncthreads();
    for (int i = threadIdx.x; i < rem * 32; i += NTH) {
        int e = i >> 5, s = (i & 31) * 4;
        const float* rp = (const float*)((char*)sm->Ah + (size_t)e * (SA * 2));
        float4 v = *(const float4*)&rp[s];
        red4(dst + (size_t)sm->colI[e] * 128 + s, v);
    }
}

// ---- fused prep: weights->fp16T, zero x1/x2out, split x, split ea ----
__global__ void prep_all(const float* __restrict__ w0, const float* __restrict__ w1,
                         const float* __restrict__ w2, const float* __restrict__ w3,
                         const float* __restrict__ w4, const float* __restrict__ w5,
                         const float* __restrict__ w6, const float* __restrict__ w7,
                         __half* __restrict__ dw, float* __restrict__ x2out,
                         const float* __restrict__ x, const float* __restrict__ ea)
{
    const size_t gtid = (size_t)blockIdx.x * blockDim.x + threadIdx.x;
    const size_t gstride = (size_t)gridDim.x * blockDim.x;

    for (size_t idx = gtid; idx < 229376; idx += gstride) {
        const int offs[9] = {0, 49152, 65536, 98304, 114688, 147456, 163840, 212992, 229376};
        const int Ks[8]   = {384, 128, 256, 128, 256, 128, 384, 128};
        const float* ws[8] = {w0, w1, w2, w3, w4, w5, w6, w7};
        int m = 0;
        while ((int)idx >= offs[m + 1]) m++;
        int local = (int)idx - offs[m];
        int K = Ks[m];
        int n = local / K;
        int k = local - n * K;
        dw[idx] = __float2half_rn(ws[m][(size_t)k * 128 + n]);
    }
    for (size_t i = gtid; i < (size_t)NN * 128; i += gstride) {
        g_x1[i] = 0.f;
        x2out[i] = 0.f;
    }
    for (size_t i = gtid; i < (size_t)NN * 32; i += gstride) {
        float4 v = ((const float4*)x)[i];
        __half h0,l0,h1,l1,h2,l2,h3,l3;
        split2(v.x,h0,l0); split2(v.y,h1,l1); split2(v.z,h2,l2); split2(v.w,h3,l3);
        __half2 a,b;
        a.x=h0; a.y=h1; b.x=h2; b.y=h3;
        ((__half2*)g_xh)[i*2] = a; ((__half2*)g_xh)[i*2+1] = b;
        a.x=l0; a.y=l1; b.x=l2; b.y=l3;
        ((__half2*)g_xl)[i*2] = a; ((__half2*)g_xl)[i*2+1] = b;
    }
    for (size_t i = gtid; i < (size_t)NE * 32; i += gstride) {
        float4 v = ((const float4*)ea)[i];
        __half h0,l0,h1,l1,h2,l2,h3,l3;
        split2(v.x,h0,l0); split2(v.y,h1,l1); split2(v.z,h2,l2); split2(v.w,h3,l3);
        __half2 a,b;
        a.x=h0; a.y=h1; b.x=h2; b.y=h3;
        ((__half2*)g_e1h)[i*2] = a; ((__half2*)g_e1h)[i*2+1] = b;
        a.x=l0; a.y=l1; b.x=l2; b.y=l3;
        ((__half2*)g_e1l)[i*2] = a; ((__half2*)g_e1l)[i*2+1] = b;
    }
}

__global__ void prep_split(const float* __restrict__ src, __half* __restrict__ dh,
                           __half* __restrict__ dl, size_t n4)
{
    for (size_t i = (size_t)blockIdx.x * blockDim.x + threadIdx.x; i < n4;
         i += (size_t)gridDim.x * blockDim.x) {
        float4 v = ((const float4*)src)[i];
        __half h0,l0,h1,l1,h2,l2,h3,l3;
        split2(v.x,h0,l0); split2(v.y,h1,l1); split2(v.z,h2,l2); split2(v.w,h3,l3);
        __half2 a,b;
        a.x=h0; a.y=h1; b.x=h2; b.y=h3;
        ((__half2*)dh)[i*2] = a; ((__half2*)dh)[i*2+1] = b;
        a.x=l0; a.y=l1; b.x=l2; b.y=l3;
        ((__half2*)dl)[i*2] = a; ((__half2*)dl)[i*2+1] = b;
    }
}

__device__ __forceinline__ void gather_idx(SM* sm, int seg,
    const __half* __restrict__ srch, const __half* __restrict__ srcl, const int* idx)
{
    u32 ah = cvta(sm->Ah), al = cvta(sm->Al);
    for (int i = threadIdx.x; i < TILE * 16; i += NTH) {
        int e = i >> 4, s = (i & 15) * 8;
        size_t r = (size_t)idx[e];
        u32 off = (u32)((e * SA + seg + s) * 2);
        cpasync16(ah + off, srch + r * 128 + s);
        cpasync16(al + off, srcl + r * 128 + s);
    }
}
__device__ __forceinline__ void gather_edge(SM* sm, int seg,
    const __half* __restrict__ srch, const __half* __restrict__ srcl, int e0)
{
    u32 ah = cvta(sm->Ah), al = cvta(sm->Al);
    for (int i = threadIdx.x; i < TILE * 16; i += NTH) {
        int e = i >> 4, s = (i & 15) * 8;
        size_t r = (size_t)min(e0 + e, NE - 1);
        u32 off = (u32)((e * SA + seg + s) * 2);
        cpasync16(ah + off, srch + r * 128 + s);
        cpasync16(al + off, srcl + r * 128 + s);
    }
}

__device__ __forceinline__ void load_idx(SM* sm, const int* row, const int* col, int e0)
{
    const int tid = threadIdx.x;
    if (tid < TILE)
        sm->rowI[tid] = (e0 + tid < NE) ? row[e0 + tid] : 0;
    else if (tid < 2 * TILE)
        sm->colI[tid - TILE] = (e0 + tid - TILE < NE) ? col[e0 + tid - TILE] : 0;
}

// ---- Phase A ----
__global__ void __launch_bounds__(NTH, 1)
phaseA(const int* __restrict__ row, const int* __restrict__ col,
       const float* __restrict__ e1b1, const float* __restrict__ e1b2,
       const float* __restrict__ n1b1, const float* __restrict__ n1b2)
{
    extern __shared__ char raw[];
    SM* sm = (SM*)raw;
    const int tid = threadIdx.x;
    const int e0 = blockIdx.x * TILE;
    const int rem = min(TILE, NE - e0);

    load_idx(sm, row, col, e0);
    __syncthreads();

    stage_w(sm, 0, g_w + W_E1W1, 384, 0);
    gather_idx(sm, 0, g_xh, g_xl, sm->rowI);
    cp_commit();                                  // G1: W chunk0 + seg0
    gather_idx(sm, 128, g_xh, g_xl, sm->colI);
    gather_edge(sm, 256, g_e1h, g_e1l, e0);       // ea-split pre-phase-A
    cp_commit();                                  // G2: rest
    if (tid < 128) sm->b1[tid] = e1b1[tid];

    float C[3][4][4];
    // MLP1 L1: K=384, chunks bufs 0,1,0 -> free buf1
    run_gemm(sm, 0, 384, g_w + W_E1W1, C, 1, 0);
    stage_w(sm, 1, g_w + W_E1W2, 128, 0);         // hoisted into free buf1
    cp_commit();
    __syncthreads();                              // all warps done reading A[256,384)
    hidden_epilogue(sm, C);
    if (tid < 128) sm->b2[tid] = e1b2[tid];
    run_gemm_1p(sm, 256, C, 1);                   // reads buf1 -> free buf0
    stage_w(sm, 0, g_w + W_N1W1, 256, 0);         // hoisted into buf0
    cp_commit();
    {   // e1 -> smem cols [128,256)  (disjoint from layer2 reads [256,384))
        const int lane = tid & 31, wid = tid >> 5;
        const int wM = wid >> 2, wN = wid & 3, g = lane >> 2, q = (lane & 3) * 2;
#pragma unroll
        for (int mi = 0; mi < 3; mi++)
#pragma unroll
            for (int nb = 0; nb < 4; nb++) {
                int r = wM * 48 + mi * 16 + g, c = wN * 32 + nb * 8 + q;
                float b0 = sm->b2[c], b1v = sm->b2[c + 1];
                store_h2(&sm->Ah[r * SA + 128 + c], &sm->Al[r * SA + 128 + c],
                         C[mi][nb][0] + b0, C[mi][nb][1] + b1v);
                store_h2(&sm->Ah[(r + 8) * SA + 128 + c], &sm->Al[(r + 8) * SA + 128 + c],
                         C[mi][nb][2] + b0, C[mi][nb][3] + b1v);
            }
    }
    if (tid < 128) sm->b1[tid] = n1b1[tid];
    __syncthreads();
    for (int i = tid; i < TILE * 16; i += NTH) {
        int e = i >> 4, s = (i & 15) * 8;
        if (e < rem) {
            *(uint4*)&g_e1h[(size_t)(e0 + e) * 128 + s] = *(const uint4*)&sm->Ah[e * SA + 128 + s];
            *(uint4*)&g_e1l[(size_t)(e0 + e) * 128 + s] = *(const uint4*)&sm->Al[e * SA + 128 + s];
        }
    }
    // MLP2 L1: K=256, chunks bufs 0,1 -> free buf0
    run_gemm(sm, 0, 256, g_w + W_N1W1, C, 0, 0);
    stage_w(sm, 0, g_w + W_N1W2, 128, 0);         // hoisted into buf0
    cp_commit();
    hidden_epilogue(sm, C);                        // [256,384) disjoint from reads [0,256)
    if (tid < 128) sm->b2[tid] = n1b2[tid];
    run_gemm_1p(sm, 256, C, 0);
    scatter_v4(sm, C, g_x1, rem);
}

// ---- Phase B ----
__global__ void __launch_bounds__(NTH, 1)
phaseB(const int* __restrict__ row, const int* __restrict__ col,
       const float* __restrict__ n2b1, const float* __restrict__ n2b2,
       float* __restrict__ x2out)
{
    extern __shared__ char raw[];
    SM* sm = (SM*)raw;
    const int tid = threadIdx.x;
    const int e0 = blockIdx.x * TILE;
    const int rem = min(TILE, NE - e0);

    load_idx(sm, row, col, e0);
    __syncthreads();

    stage_w(sm, 0, g_w + W_N2W1, 256, 0);
    gather_idx(sm, 0, g_x1h, g_x1l, sm->rowI);
    cp_commit();                                  // G1
    gather_edge(sm, 128, g_e1h, g_e1l, e0);
    cp_commit();                                  // G2
    if (tid < 128) sm->b1[tid] = n2b1[tid];

    float C[3][4][4];
    run_gemm(sm, 0, 256, g_w + W_N2W1, C, 1, 0);  // bufs 0,1 -> free buf0
    stage_w(sm, 0, g_w + W_N2W2, 128, 0);         // hoisted
    cp_commit();
    hidden_epilogue(sm, C);                        // [256,384) disjoint from reads [0,256)
    if (tid < 128) sm->b2[tid] = n2b2[tid];
    run_gemm_1p(sm, 256, C, 0);
    scatter_v4(sm, C, x2out, rem);
}

// ---- Phase C ----
__global__ void __launch_bounds__(NTH, 1)
phaseC(const int* __restrict__ row, const int* __restrict__ col,
       const float* __restrict__ e2b1, const float* __restrict__ e2b2,
       float* __restrict__ e2out)
{
    extern __shared__ char raw[];
    SM* sm = (SM*)raw;
    const int tid = threadIdx.x;
    const int e0 = blockIdx.x * TILE;
    const int rem = min(TILE, NE - e0);

    load_idx(sm, row, col, e0);
    __syncthreads();

    stage_w(sm, 0, g_w + W_E2W1, 384, 0);
    gather_idx(sm, 0, g_x2h, g_x2l, sm->rowI);
    cp_commit();                                  // G1
    gather_idx(sm, 128, g_x2h, g_x2l, sm->colI);
    gather_edge(sm, 256, g_e1h, g_e1l, e0);
    cp_commit();                                  // G2
    if (tid < 128) sm->b1[tid] = e2b1[tid];

    float C[3][4][4];
    run_gemm(sm, 0, 384, g_w + W_E2W1, C, 1, 0);  // bufs 0,1,0 -> free buf1
    stage_w(sm, 1, g_w + W_E2W2, 128, 0);         // hoisted into buf1
    cp_commit();
    __syncthreads();
    hidden_epilogue(sm, C);
    if (tid < 128) sm->b2[tid] = e2b2[tid];
    run_gemm_1p(sm, 256, C, 1);

    // e2 direct: stage fp32 (bytes [0,512) disjoint from reads), then store
    stage_c_f32(sm, C);
    __syncthreads();
    for (int i = tid; i < TILE * 32; i += NTH) {
        int e = i >> 5, s = (i & 31) * 4;
        if (e < rem) {
            const float* rp = (const float*)((char*)sm->Ah + (size_t)e * (SA * 2));
            *(float4*)&e2out[(size_t)(e0 + e) * 128 + s] = *(const float4*)&rp[s];
        }
    }
}

extern "C" void kernel_launch(void* const* d_in, const int* in_sizes, int n_in,
                              void* d_out, int out_size)
{
    const float* x    = (const float*)d_in[0];
    const float* ea   = (const float*)d_in[1];
    const int*   ei   = (const int*)d_in[2];
    const float* e1w1 = (const float*)d_in[3];
    const float* e1b1 = (const float*)d_in[4];
    const float* e1w2 = (const float*)d_in[5];
    const float* e1b2 = (const float*)d_in[6];
    const float* n1w1 = (const float*)d_in[7];
    const float* n1b1 = (const float*)d_in[8];
    const float* n1w2 = (const float*)d_in[9];
    const float* n1b2 = (const float*)d_in[10];
    const float* n2w1 = (const float*)d_in[11];
    const float* n2b1 = (const float*)d_in[12];
    const float* n2w2 = (const float*)d_in[13];
    const float* n2b2 = (const float*)d_in[14];
    const float* e2w1 = (const float*)d_in[15];
    const float* e2b1 = (const float*)d_in[16];
    const float* e2w2 = (const float*)d_in[17];
    const float* e2b2 = (const float*)d_in[18];

    const int* row = ei;
    const int* col = ei + NE;

    float* out = (float*)d_out;
    float* x2  = out;
    float* e2o = out + (size_t)NN * 128;

    __half *w, *x1h, *x1l, *x2h, *x2l;
    float* x1p;
    cudaGetSymbolAddress((void**)&w, g_w);
    cudaGetSymbolAddress((void**)&x1h, g_x1h);
    cudaGetSymbolAddress((void**)&x1l, g_x1l);
    cudaGetSymbolAddress((void**)&x2h, g_x2h);
    cudaGetSymbolAddress((void**)&x2l, g_x2l);
    cudaGetSymbolAddress((void**)&x1p, g_x1);

    prep_all<<<2048, 256>>>(e1w1, e1w2, n1w1, n1w2, n2w1, n2w2, e2w1, e2w2,
                            w, x2, x, ea);

    int smemBytes = (int)sizeof(SM);
    cudaFuncSetAttribute(phaseA, cudaFuncAttributeMaxDynamicSharedMemorySize, smemBytes);
    cudaFuncSetAttribute(phaseB, cudaFuncAttributeMaxDynamicSharedMemorySize, smemBytes);
    cudaFuncSetAttribute(phaseC, cudaFuncAttributeMaxDynamicSharedMemorySize, smemBytes);

    phaseA<<<NBLK, NTH, smemBytes>>>(row, col, e1b1, e1b2, n1b1, n1b2);
    prep_split<<<512, 256>>>(x1p, x1h, x1l, (size_t)NN * 32);
    phaseB<<<NBLK, NTH, smemBytes>>>(row, col, n2b1, n2b2, x2);
    prep_split<<<512, 256>>>(x2, x2h, x2l, (size_t)NN * 32);
    phaseC<<<NBLK, NTH, smemBytes>>>(row, col, e2b1, e2b2, e2o);
}

// round 15
// speedup vs baseline: 1.5893x; 1.5893x over previous
#include <cuda_runtime.h>
#include <cuda_fp16.h>
#include <cstdint>

#define NN 40000
#define NE 640000
#define TILE 96
#define NTH 256
#define NBLK ((NE + TILE - 1) / TILE)   // 6667 (last tile: 64 edges)
#define SA 392   // A-plane smem stride (halves)
#define SW 72    // W-plane smem stride (halves)

typedef unsigned int u32;

// ---- device scratch ----
__device__ __half g_e1h[(size_t)NE * 128];   // ea-split before phase A, e1-split after
__device__ __half g_e1l[(size_t)NE * 128];
__device__ float  g_x1[(size_t)NN * 128];
__device__ __half g_xh[(size_t)NN * 128];
__device__ __half g_xl[(size_t)NN * 128];
__device__ __half g_x1h[(size_t)NN * 128];
__device__ __half g_x1l[(size_t)NN * 128];
__device__ __half g_x2h[(size_t)NN * 128];
__device__ __half g_x2l[(size_t)NN * 128];
__device__ __half g_w[229376];               // single fp16 plane, transposed [n][k]

#define W_E1W1 0
#define W_E1W2 49152
#define W_N1W1 65536
#define W_N1W2 98304
#define W_N2W1 114688
#define W_N2W2 147456
#define W_E2W1 163840
#define W_E2W2 212992

struct SM {
    __half Ah[TILE * SA];     // 75264 B ; per-row bytes [0,512) double as fp32 staging
    __half Al[TILE * SA];     // 75264 B
    __half W[2][128 * SW];    // 36864 B
    float b1[128];
    float b2[128];
    int rowI[TILE];
    int colI[TILE];
};                            // ~189 KB

// ---- helpers ----
__device__ __forceinline__ u32 cvta(const void* p) {
    return (u32)__cvta_generic_to_shared(p);
}
__device__ __forceinline__ void cpasync16(u32 dst, const void* src) {
    asm volatile("cp.async.cg.shared.global [%0], [%1], 16;" :: "r"(dst), "l"(src) : "memory");
}
__device__ __forceinline__ void cp_commit() {
    asm volatile("cp.async.commit_group;" ::: "memory");
}
__device__ __forceinline__ void cp_wait0() {
    asm volatile("cp.async.wait_group 0;" ::: "memory");
}
__device__ __forceinline__ void cp_wait1() {
    asm volatile("cp.async.wait_group 1;" ::: "memory");
}
__device__ __forceinline__ void pair_bar(int wN) {
    asm volatile("bar.sync %0, 64;" :: "r"(1 + wN) : "memory");
}
__device__ __forceinline__ void ldsm4(u32 addr, u32& r0, u32& r1, u32& r2, u32& r3) {
    asm volatile("ldmatrix.sync.aligned.m8n8.x4.shared.b16 {%0,%1,%2,%3}, [%4];"
                 : "=r"(r0), "=r"(r1), "=r"(r2), "=r"(r3) : "r"(addr));
}
__device__ __forceinline__ void mma16816(float* c, const u32* a, const u32* b) {
    asm volatile("mma.sync.aligned.m16n8k16.row.col.f32.f16.f16.f32 "
                 "{%0,%1,%2,%3}, {%4,%5,%6,%7}, {%8,%9}, {%0,%1,%2,%3};"
                 : "+f"(c[0]), "+f"(c[1]), "+f"(c[2]), "+f"(c[3])
                 : "r"(a[0]), "r"(a[1]), "r"(a[2]), "r"(a[3]), "r"(b[0]), "r"(b[1]));
}
__device__ __forceinline__ void red4(float* p, float4 v) {
    asm volatile("red.global.add.v4.f32 [%0], {%1,%2,%3,%4};"
                 :: "l"(p), "f"(v.x), "f"(v.y), "f"(v.z), "f"(v.w) : "memory");
}
__device__ __forceinline__ void split2(float x, __half& h, __half& l) {
    h = __float2half_rn(x);
    l = __float2half_rn(x - __half2float(h));
}
__device__ __forceinline__ void store_h2(__half* ph, __half* pl, float x0, float x1) {
    __half h0,l0,h1,l1; split2(x0,h0,l0); split2(x1,h1,l1);
    __half2 t;
    t.x=h0; t.y=h1; *(__half2*)ph = t;
    t.x=l0; t.y=l1; *(__half2*)pl = t;
}

// PAIR-scoped staging: the two warps sharing wN stage their own 32 W rows
// [wN*32, wN*32+32) of the 64-k chunk. 64 threads, 4 cp16 each.
__device__ __forceinline__ void stage_w_pair(SM* sm, int buf,
    const __half* __restrict__ gw, int K, int k0)
{
    const int lane = threadIdx.x & 31, wid = threadIdx.x >> 5;
    const int wM = wid >> 2, wN = wid & 3;
    const int t = wM * 32 + lane;          // 0..63 within pair
    u32 d = cvta(&sm->W[buf][0]);
#pragma unroll
    for (int i = 0; i < 4; i++) {
        int idx = t + i * 64;              // 0..255 ; 8 cp16 per row
        int r = wN * 32 + (idx >> 3);
        int s = (idx & 7) << 3;
        cpasync16(d + (u32)((r * SW + s) * 2), gw + (size_t)r * K + k0 + s);
    }
}

// GEMM (2-plane A): C[96 x 128] += (Ah+Al) x W^T. 8 warps, warp tile 48x32.
// W double-buffered, PAIR-staged. Caller staged+committed chunk0 into buf0.
// nBS: number of leading chunks using a BLOCK sync (cross-thread A visibility
// for prologue gathers); later chunks use the cheap pair barrier (W-only dep).
// firstWait=1: allow ONE trailing pending group at chunk0.
__device__ __forceinline__ void run_gemm(SM* sm, int aCol, int K,
    const __half* __restrict__ gw, float C[3][4][4], int firstWait, int nBS)
{
    const int tid = threadIdx.x, lane = tid & 31, wid = tid >> 5;
    const int wM = wid >> 2, wN = wid & 3;
#pragma unroll
    for (int i = 0; i < 3; i++)
#pragma unroll
        for (int j = 0; j < 4; j++)
#pragma unroll
            for (int q = 0; q < 4; q++) C[i][j][q] = 0.f;

    const u32 ah_base = cvta(sm->Ah), al_base = cvta(sm->Al);
    const u32 w_base[2] = { cvta(&sm->W[0][0]), cvta(&sm->W[1][0]) };

    const int aRow0 = wM * 48 + (lane & 15);
    const int aColL = (lane >> 4) * 8;
    const int bRowL = (lane & 7) + ((lane & 16) >> 1);
    const int bColL = lane & 8;

    const int nchunk = K >> 6;
    for (int c = 0; c < nchunk; c++) {
        if (c == 0 && firstWait) cp_wait1(); else cp_wait0();
        if (c < nBS) __syncthreads(); else pair_bar(wN);
        if (c + 1 < nchunk) {
            stage_w_pair(sm, (c + 1) & 1, gw, K, (c + 1) << 6);
            cp_commit();
        }
        const int buf = c & 1, k0 = c << 6;
#pragma unroll
        for (int kk = 0; kk < 64; kk += 16) {
            u32 a_h[3][4], a_l[3][4];
#pragma unroll
            for (int mi = 0; mi < 3; mi++) {
                u32 off = (u32)(((aRow0 + mi * 16) * SA + aCol + k0 + kk + aColL) * 2);
                ldsm4(ah_base + off, a_h[mi][0], a_h[mi][1], a_h[mi][2], a_h[mi][3]);
                ldsm4(al_base + off, a_l[mi][0], a_l[mi][1], a_l[mi][2], a_l[mi][3]);
            }
            u32 b[4][2];
#pragma unroll
            for (int pr = 0; pr < 2; pr++) {
                u32 off = (u32)(((wN * 32 + pr * 16 + bRowL) * SW + kk + bColL) * 2);
                ldsm4(w_base[buf] + off, b[2*pr][0], b[2*pr][1], b[2*pr+1][0], b[2*pr+1][1]);
            }
#pragma unroll
            for (int mi = 0; mi < 3; mi++)
#pragma unroll
                for (int nb = 0; nb < 4; nb++) {
                    mma16816(C[mi][nb], a_h[mi], b[nb]);
                    mma16816(C[mi][nb], a_l[mi], b[nb]);
                }
        }
    }
}

// GEMM (1-plane A, fp16 hidden): C += Ah x W^T. K=128, chunk0 pair-staged by
// caller in buf0. chunk0 uses BLOCK sync (hidden A writes visibility);
// chunk1 uses pair barrier (W-only dep).
__device__ __forceinline__ void run_gemm_1p(SM* sm, int aCol,
    const __half* __restrict__ gw, float C[3][4][4])
{
    const int tid = threadIdx.x, lane = tid & 31, wid = tid >> 5;
    const int wM = wid >> 2, wN = wid & 3;
#pragma unroll
    for (int i = 0; i < 3; i++)
#pragma unroll
        for (int j = 0; j < 4; j++)
#pragma unroll
            for (int q = 0; q < 4; q++) C[i][j][q] = 0.f;

    const u32 ah_base = cvta(sm->Ah);
    const u32 w_base[2] = { cvta(&sm->W[0][0]), cvta(&sm->W[1][0]) };

    const int aRow0 = wM * 48 + (lane & 15);
    const int aColL = (lane >> 4) * 8;
    const int bRowL = (lane & 7) + ((lane & 16) >> 1);
    const int bColL = lane & 8;

#pragma unroll
    for (int c = 0; c < 2; c++) {
        cp_wait0();
        if (c == 0) __syncthreads(); else pair_bar(wN);
        if (c == 0) {
            stage_w_pair(sm, 1, gw, 128, 64);
            cp_commit();
        }
        const int buf = c, k0 = c << 6;
#pragma unroll
        for (int kk = 0; kk < 64; kk += 16) {
            u32 a_h[3][4];
#pragma unroll
            for (int mi = 0; mi < 3; mi++) {
                u32 off = (u32)(((aRow0 + mi * 16) * SA + aCol + k0 + kk + aColL) * 2);
                ldsm4(ah_base + off, a_h[mi][0], a_h[mi][1], a_h[mi][2], a_h[mi][3]);
            }
            u32 b[4][2];
#pragma unroll
            for (int pr = 0; pr < 2; pr++) {
                u32 off = (u32)(((wN * 32 + pr * 16 + bRowL) * SW + kk + bColL) * 2);
                ldsm4(w_base[buf] + off, b[2*pr][0], b[2*pr][1], b[2*pr+1][0], b[2*pr+1][1]);
            }
#pragma unroll
            for (int mi = 0; mi < 3; mi++)
#pragma unroll
                for (int nb = 0; nb < 4; nb++)
                    mma16816(C[mi][nb], a_h[mi], b[nb]);
        }
    }
}

// fragment owner: rows r=wM*48+mi*16+(lane>>2), r+8 ; cols c=wN*32+nb*8+(lane&3)*2
// hidden = relu(C+b1) as single fp16 plane -> Ah cols [256,384)
__device__ __forceinline__ void hidden_epilogue(SM* sm, float C[3][4][4]) {
    const int lane = threadIdx.x & 31, wid = threadIdx.x >> 5;
    const int wM = wid >> 2, wN = wid & 3, g = lane >> 2, q = (lane & 3) * 2;
#pragma unroll
    for (int mi = 0; mi < 3; mi++)
#pragma unroll
        for (int nb = 0; nb < 4; nb++) {
            int r = wM * 48 + mi * 16 + g, c = wN * 32 + nb * 8 + q;
            float b0 = sm->b1[c], b1v = sm->b1[c + 1];
            __half2 t0, t1;
            t0.x = __float2half_rn(fmaxf(C[mi][nb][0] + b0, 0.f));
            t0.y = __float2half_rn(fmaxf(C[mi][nb][1] + b1v, 0.f));
            t1.x = __float2half_rn(fmaxf(C[mi][nb][2] + b0, 0.f));
            t1.y = __float2half_rn(fmaxf(C[mi][nb][3] + b1v, 0.f));
            *(__half2*)&sm->Ah[r * SA + 256 + c] = t0;
            *(__half2*)&sm->Ah[(r + 8) * SA + 256 + c] = t1;
        }
}

// stage C (+bias) as fp32 into Ah per-row bytes [0,512) — disjoint from the last
// GEMM's A reads at half-cols [256,384) = bytes [512,768).
__device__ __forceinline__ void stage_c_f32(SM* sm, float C[3][4][4]) {
    const int lane = threadIdx.x & 31, wid = threadIdx.x >> 5;
    const int wM = wid >> 2, wN = wid & 3, g = lane >> 2, q = (lane & 3) * 2;
#pragma unroll
    for (int mi = 0; mi < 3; mi++)
#pragma unroll
        for (int nb = 0; nb < 4; nb++) {
            int r = wM * 48 + mi * 16 + g, c = wN * 32 + nb * 8 + q;
            float b0 = sm->b2[c], b1v = sm->b2[c + 1];
            float* p0 = (float*)((char*)sm->Ah + (size_t)r * (SA * 2));
            float* p1 = (float*)((char*)sm->Ah + (size_t)(r + 8) * (SA * 2));
            *(float2*)&p0[c] = make_float2(C[mi][nb][0] + b0, C[mi][nb][1] + b1v);
            *(float2*)&p1[c] = make_float2(C[mi][nb][2] + b0, C[mi][nb][3] + b1v);
        }
}

// v4 scatter from the fp32 staging region
__device__ __forceinline__ void scatter_v4(SM* sm, float C[3][4][4],
                                           float* __restrict__ dst, int rem)
{
    stage_c_f32(sm, C);
    __syncthreads();
    for (int i = threadIdx.x; i < rem * 32; i += NTH) {
        int e = i >> 5, s = (i & 31) * 4;
        const float* rp = (const float*)((char*)sm->Ah + (size_t)e * (SA * 2));
        float4 v = *(const float4*)&rp[s];
        red4(dst + (size_t)sm->colI[e] * 128 + s, v);
    }
}

// ---- fused prep: weights->fp16T, zero x1/x2out, split x, split ea ----
__global__ void prep_all(const float* __restrict__ w0, const float* __restrict__ w1,
                         const float* __restrict__ w2, const float* __restrict__ w3,
                         const float* __restrict__ w4, const float* __restrict__ w5,
                         const float* __restrict__ w6, const float* __restrict__ w7,
                         __half* __restrict__ dw, float* __restrict__ x2out,
                         const float* __restrict__ x, const float* __restrict__ ea)
{
    const size_t gtid = (size_t)blockIdx.x * blockDim.x + threadIdx.x;
    const size_t gstride = (size_t)gridDim.x * blockDim.x;

    for (size_t idx = gtid; idx < 229376; idx += gstride) {
        const int offs[9] = {0, 49152, 65536, 98304, 114688, 147456, 163840, 212992, 229376};
        const int Ks[8]   = {384, 128, 256, 128, 256, 128, 384, 128};
        const float* ws[8] = {w0, w1, w2, w3, w4, w5, w6, w7};
        int m = 0;
        while ((int)idx >= offs[m + 1]) m++;
        int local = (int)idx - offs[m];
        int K = Ks[m];
        int n = local / K;
        int k = local - n * K;
        dw[idx] = __float2half_rn(ws[m][(size_t)k * 128 + n]);
    }
    for (size_t i = gtid; i < (size_t)NN * 128; i += gstride) {
        g_x1[i] = 0.f;
        x2out[i] = 0.f;
    }
    for (size_t i = gtid; i < (size_t)NN * 32; i += gstride) {
        float4 v = ((const float4*)x)[i];
        __half h0,l0,h1,l1,h2,l2,h3,l3;
        split2(v.x,h0,l0); split2(v.y,h1,l1); split2(v.z,h2,l2); split2(v.w,h3,l3);
        __half2 a,b;
        a.x=h0; a.y=h1; b.x=h2; b.y=h3;
        ((__half2*)g_xh)[i*2] = a; ((__half2*)g_xh)[i*2+1] = b;
        a.x=l0; a.y=l1; b.x=l2; b.y=l3;
        ((__half2*)g_xl)[i*2] = a; ((__half2*)g_xl)[i*2+1] = b;
    }
    for (size_t i = gtid; i < (size_t)NE * 32; i += gstride) {
        float4 v = ((const float4*)ea)[i];
        __half h0,l0,h1,l1,h2,l2,h3,l3;
        split2(v.x,h0,l0); split2(v.y,h1,l1); split2(v.z,h2,l2); split2(v.w,h3,l3);
        __half2 a,b;
        a.x=h0; a.y=h1; b.x=h2; b.y=h3;
        ((__half2*)g_e1h)[i*2] = a; ((__half2*)g_e1h)[i*2+1] = b;
        a.x=l0; a.y=l1; b.x=l2; b.y=l3;
        ((__half2*)g_e1l)[i*2] = a; ((__half2*)g_e1l)[i*2+1] = b;
    }
}

__global__ void prep_split(const float* __restrict__ src, __half* __restrict__ dh,
                           __half* __restrict__ dl, size_t n4)
{
    for (size_t i = (size_t)blockIdx.x * blockDim.x + threadIdx.x; i < n4;
         i += (size_t)gridDim.x * blockDim.x) {
        float4 v = ((const float4*)src)[i];
        __half h0,l0,h1,l1,h2,l2,h3,l3;
        split2(v.x,h0,l0); split2(v.y,h1,l1); split2(v.z,h2,l2); split2(v.w,h3,l3);
        __half2 a,b;
        a.x=h0; a.y=h1; b.x=h2; b.y=h3;
        ((__half2*)dh)[i*2] = a; ((__half2*)dh)[i*2+1] = b;
        a.x=l0; a.y=l1; b.x=l2; b.y=l3;
        ((__half2*)dl)[i*2] = a; ((__half2*)dl)[i*2+1] = b;
    }
}

__device__ __forceinline__ void gather_idx(SM* sm, int seg,
    const __half* __restrict__ srch, const __half* __restrict__ srcl, const int* idx)
{
    u32 ah = cvta(sm->Ah), al = cvta(sm->Al);
    for (int i = threadIdx.x; i < TILE * 16; i += NTH) {
        int e = i >> 4, s = (i & 15) * 8;
        size_t r = (size_t)idx[e];
        u32 off = (u32)((e * SA + seg + s) * 2);
        cpasync16(ah + off, srch + r * 128 + s);
        cpasync16(al + off, srcl + r * 128 + s);
    }
}
__device__ __forceinline__ void gather_edge(SM* sm, int seg,
    const __half* __restrict__ srch, const __half* __restrict__ srcl, int e0)
{
    u32 ah = cvta(sm->Ah), al = cvta(sm->Al);
    for (int i = threadIdx.x; i < TILE * 16; i += NTH) {
        int e = i >> 4, s = (i & 15) * 8;
        size_t r = (size_t)min(e0 + e, NE - 1);
        u32 off = (u32)((e * SA + seg + s) * 2);
        cpasync16(ah + off, srch + r * 128 + s);
        cpasync16(al + off, srcl + r * 128 + s);
    }
}

__device__ __forceinline__ void load_idx(SM* sm, const int* row, const int* col, int e0)
{
    const int tid = threadIdx.x;
    if (tid < TILE)
        sm->rowI[tid] = (e0 + tid < NE) ? row[e0 + tid] : 0;
    else if (tid < 2 * TILE)
        sm->colI[tid - TILE] = (e0 + tid - TILE < NE) ? col[e0 + tid - TILE] : 0;
}

// ---- Phase A ----
__global__ void __launch_bounds__(NTH, 1)
phaseA(const int* __restrict__ row, const int* __restrict__ col,
       const float* __restrict__ e1b1, const float* __restrict__ e1b2,
       const float* __restrict__ n1b1, const float* __restrict__ n1b2)
{
    extern __shared__ char raw[];
    SM* sm = (SM*)raw;
    const int tid = threadIdx.x;
    const int e0 = blockIdx.x * TILE;
    const int rem = min(TILE, NE - e0);

    load_idx(sm, row, col, e0);
    __syncthreads();

    stage_w_pair(sm, 0, g_w + W_E1W1, 384, 0);
    gather_idx(sm, 0, g_xh, g_xl, sm->rowI);
    cp_commit();                                  // G1: W chunk0 + seg0
    gather_idx(sm, 128, g_xh, g_xl, sm->colI);
    gather_edge(sm, 256, g_e1h, g_e1l, e0);       // ea-split pre-phase-A
    cp_commit();                                  // G2: rest
    if (tid < 128) sm->b1[tid] = e1b1[tid];

    float C[3][4][4];
    run_gemm(sm, 0, 384, g_w + W_E1W1, C, 1, 2);  // 6 chunks; c0,c1 block-sync
    stage_w_pair(sm, 0, g_w + W_E1W2, 128, 0);    // hoisted: buf0 free
    cp_commit();
    __syncthreads();                              // all warps done reading A[256,384)
    hidden_epilogue(sm, C);
    if (tid < 128) sm->b2[tid] = e1b2[tid];
    run_gemm_1p(sm, 256, g_w + W_E1W2, C);
    stage_w_pair(sm, 0, g_w + W_N1W1, 256, 0);    // hoisted
    cp_commit();
    {   // e1 -> smem cols [128,256)  (disjoint from layer2 reads [256,384))
        const int lane = tid & 31, wid = tid >> 5;
        const int wM = wid >> 2, wN = wid & 3, g = lane >> 2, q = (lane & 3) * 2;
#pragma unroll
        for (int mi = 0; mi < 3; mi++)
#pragma unroll
            for (int nb = 0; nb < 4; nb++) {
                int r = wM * 48 + mi * 16 + g, c = wN * 32 + nb * 8 + q;
                float b0 = sm->b2[c], b1v = sm->b2[c + 1];
                store_h2(&sm->Ah[r * SA + 128 + c], &sm->Al[r * SA + 128 + c],
                         C[mi][nb][0] + b0, C[mi][nb][1] + b1v);
                store_h2(&sm->Ah[(r + 8) * SA + 128 + c], &sm->Al[(r + 8) * SA + 128 + c],
                         C[mi][nb][2] + b0, C[mi][nb][3] + b1v);
            }
    }
    if (tid < 128) sm->b1[tid] = n1b1[tid];
    __syncthreads();
    for (int i = tid; i < TILE * 16; i += NTH) {
        int e = i >> 4, s = (i & 15) * 8;
        if (e < rem) {
            *(uint4*)&g_e1h[(size_t)(e0 + e) * 128 + s] = *(const uint4*)&sm->Ah[e * SA + 128 + s];
            *(uint4*)&g_e1l[(size_t)(e0 + e) * 128 + s] = *(const uint4*)&sm->Al[e * SA + 128 + s];
        }
    }
    // MLP2: input cols [0,256) = [x[row], e1] ; A visible via sync above
    run_gemm(sm, 0, 256, g_w + W_N1W1, C, 0, 0);
    stage_w_pair(sm, 0, g_w + W_N1W2, 128, 0);    // hoisted
    cp_commit();
    hidden_epilogue(sm, C);                        // [256,384) disjoint from reads [0,256)
    if (tid < 128) sm->b2[tid] = n1b2[tid];
    run_gemm_1p(sm, 256, g_w + W_N1W2, C);
    scatter_v4(sm, C, g_x1, rem);
}

// ---- Phase B ----
__global__ void __launch_bounds__(NTH, 1)
phaseB(const int* __restrict__ row, const int* __restrict__ col,
       const float* __restrict__ n2b1, const float* __restrict__ n2b2,
       float* __restrict__ x2out)
{
    extern __shared__ char raw[];
    SM* sm = (SM*)raw;
    const int tid = threadIdx.x;
    const int e0 = blockIdx.x * TILE;
    const int rem = min(TILE, NE - e0);

    load_idx(sm, row, col, e0);
    __syncthreads();

    stage_w_pair(sm, 0, g_w + W_N2W1, 256, 0);
    gather_idx(sm, 0, g_x1h, g_x1l, sm->rowI);
    cp_commit();                                  // G1
    gather_edge(sm, 128, g_e1h, g_e1l, e0);
    cp_commit();                                  // G2
    if (tid < 128) sm->b1[tid] = n2b1[tid];

    float C[3][4][4];
    run_gemm(sm, 0, 256, g_w + W_N2W1, C, 1, 2);  // c0,c1 block-sync
    stage_w_pair(sm, 0, g_w + W_N2W2, 128, 0);    // hoisted
    cp_commit();
    hidden_epilogue(sm, C);                        // [256,384) disjoint from reads [0,256)
    if (tid < 128) sm->b2[tid] = n2b2[tid];
    run_gemm_1p(sm, 256, g_w + W_N2W2, C);
    scatter_v4(sm, C, x2out, rem);
}

// ---- Phase C ----
__global__ void __launch_bounds__(NTH, 1)
phaseC(const int* __restrict__ row, const int* __restrict__ col,
       const float* __restrict__ e2b1, const float* __restrict__ e2b2,
       float* __restrict__ e2out)
{
    extern __shared__ char raw[];
    SM* sm = (SM*)raw;
    const int tid = threadIdx.x;
    const int e0 = blockIdx.x * TILE;
    const int rem = min(TILE, NE - e0);

    load_idx(sm, row, col, e0);
    __syncthreads();

    stage_w_pair(sm, 0, g_w + W_E2W1, 384, 0);
    gather_idx(sm, 0, g_x2h, g_x2l, sm->rowI);
    cp_commit();                                  // G1
    gather_idx(sm, 128, g_x2h, g_x2l, sm->colI);
    gather_edge(sm, 256, g_e1h, g_e1l, e0);
    cp_commit();                                  // G2
    if (tid < 128) sm->b1[tid] = e2b1[tid];

    float C[3][4][4];
    run_gemm(sm, 0, 384, g_w + W_E2W1, C, 1, 2);  // c0,c1 block-sync
    stage_w_pair(sm, 0, g_w + W_E2W2, 128, 0);    // hoisted
    cp_commit();
    __syncthreads();
    hidden_epilogue(sm, C);
    if (tid < 128) sm->b2[tid] = e2b2[tid];
    run_gemm_1p(sm, 256, g_w + W_E2W2, C);

    // e2 direct: stage fp32 (bytes [0,512) disjoint from reads), then store
    stage_c_f32(sm, C);
    __syncthreads();
    for (int i = tid; i < TILE * 32; i += NTH) {
        int e = i >> 5, s = (i & 31) * 4;
        if (e < rem) {
            const float* rp = (const float*)((char*)sm->Ah + (size_t)e * (SA * 2));
            *(float4*)&e2out[(size_t)(e0 + e) * 128 + s] = *(const float4*)&rp[s];
        }
    }
}

extern "C" void kernel_launch(void* const* d_in, const int* in_sizes, int n_in,
                              void* d_out, int out_size)
{
    const float* x    = (const float*)d_in[0];
    const float* ea   = (const float*)d_in[1];
    const int*   ei   = (const int*)d_in[2];
    const float* e1w1 = (const float*)d_in[3];
    const float* e1b1 = (const float*)d_in[4];
    const float* e1w2 = (const float*)d_in[5];
    const float* e1b2 = (const float*)d_in[6];
    const float* n1w1 = (const float*)d_in[7];
    const float* n1b1 = (const float*)d_in[8];
    const float* n1w2 = (const float*)d_in[9];
    const float* n1b2 = (const float*)d_in[10];
    const float* n2w1 = (const float*)d_in[11];
    const float* n2b1 = (const float*)d_in[12];
    const float* n2w2 = (const float*)d_in[13];
    const float* n2b2 = (const float*)d_in[14];
    const float* e2w1 = (const float*)d_in[15];
    const float* e2b1 = (const float*)d_in[16];
    const float* e2w2 = (const float*)d_in[17];
    const float* e2b2 = (const float*)d_in[18];

    const int* row = ei;
    const int* col = ei + NE;

    float* out = (float*)d_out;
    float* x2  = out;
    float* e2o = out + (size_t)NN * 128;

    __half *w, *x1h, *x1l, *x2h, *x2l;
    float* x1p;
    cudaGetSymbolAddress((void**)&w, g_w);
    cudaGetSymbolAddress((void**)&x1h, g_x1h);
    cudaGetSymbolAddress((void**)&x1l, g_x1l);
    cudaGetSymbolAddress((void**)&x2h, g_x2h);
    cudaGetSymbolAddress((void**)&x2l, g_x2l);
    cudaGetSymbolAddress((void**)&x1p, g_x1);

    prep_all<<<2048, 256>>>(e1w1, e1w2, n1w1, n1w2, n2w1, n2w2, e2w1, e2w2,
                            w, x2, x, ea);

    int smemBytes = (int)sizeof(SM);
    cudaFuncSetAttribute(phaseA, cudaFuncAttributeMaxDynamicSharedMemorySize, smemBytes);
    cudaFuncSetAttribute(phaseB, cudaFuncAttributeMaxDynamicSharedMemorySize, smemBytes);
    cudaFuncSetAttribute(phaseC, cudaFuncAttributeMaxDynamicSharedMemorySize, smemBytes);

    phaseA<<<NBLK, NTH, smemBytes>>>(row, col, e1b1, e1b2, n1b1, n1b2);
    prep_split<<<512, 256>>>(x1p, x1h, x1l, (size_t)NN * 32);
    phaseB<<<NBLK, NTH, smemBytes>>>(row, col, n2b1, n2b2, x2);
    prep_split<<<512, 256>>>(x2, x2h, x2l, (size_t)NN * 32);
    phaseC<<<NBLK, NTH, smemBytes>>>(row, col, e2b1, e2b2, e2o);
}

// round 16
// speedup vs baseline: 2.1338x; 1.3426x over previous
#include <cuda_runtime.h>
#include <cuda_fp16.h>
#include <cstdint>

#define NN 40000
#define NE 640000
#define TILE 96
#define NTH 256
#define NBLK ((NE + TILE - 1) / TILE)   // 6667 (last tile: 64 edges)
#define SA 392   // A-plane smem stride (halves)
#define SW 72    // W-plane smem stride (halves)

typedef unsigned int u32;

// ---- device scratch (single fp16 plane activations) ----
__device__ __half g_e1[(size_t)NE * 128];    // ea before phase A, e1 after
__device__ float  g_x1[(size_t)NN * 128];
__device__ __half g_x[(size_t)NN * 128];
__device__ __half g_x1f[(size_t)NN * 128];
__device__ __half g_x2f[(size_t)NN * 128];
__device__ __half g_w[229376];               // fp16, transposed [n][k]

#define W_E1W1 0
#define W_E1W2 49152
#define W_N1W1 65536
#define W_N1W2 98304
#define W_N2W1 114688
#define W_N2W2 147456
#define W_E2W1 163840
#define W_E2W2 212992

struct SM {
    __half Ah[TILE * SA];     // 75264 B ; per-row bytes [0,512) double as fp32 staging
    __half W[2][128 * SW];    // 36864 B
    float b1[128];
    float b2[128];
    int rowI[TILE];
    int colI[TILE];
};                            // ~114 KB

// ---- helpers ----
__device__ __forceinline__ u32 cvta(const void* p) {
    return (u32)__cvta_generic_to_shared(p);
}
__device__ __forceinline__ void cpasync16(u32 dst, const void* src) {
    asm volatile("cp.async.cg.shared.global [%0], [%1], 16;" :: "r"(dst), "l"(src) : "memory");
}
__device__ __forceinline__ void cp_commit() {
    asm volatile("cp.async.commit_group;" ::: "memory");
}
__device__ __forceinline__ void cp_wait0() {
    asm volatile("cp.async.wait_group 0;" ::: "memory");
}
__device__ __forceinline__ void cp_wait1() {
    asm volatile("cp.async.wait_group 1;" ::: "memory");
}
__device__ __forceinline__ void pair_bar(int wN) {
    asm volatile("bar.sync %0, 64;" :: "r"(1 + wN) : "memory");
}
__device__ __forceinline__ void ldsm4(u32 addr, u32& r0, u32& r1, u32& r2, u32& r3) {
    asm volatile("ldmatrix.sync.aligned.m8n8.x4.shared.b16 {%0,%1,%2,%3}, [%4];"
                 : "=r"(r0), "=r"(r1), "=r"(r2), "=r"(r3) : "r"(addr));
}
__device__ __forceinline__ void mma16816(float* c, const u32* a, const u32* b) {
    asm volatile("mma.sync.aligned.m16n8k16.row.col.f32.f16.f16.f32 "
                 "{%0,%1,%2,%3}, {%4,%5,%6,%7}, {%8,%9}, {%0,%1,%2,%3};"
                 : "+f"(c[0]), "+f"(c[1]), "+f"(c[2]), "+f"(c[3])
                 : "r"(a[0]), "r"(a[1]), "r"(a[2]), "r"(a[3]), "r"(b[0]), "r"(b[1]));
}
__device__ __forceinline__ void red4(float* p, float4 v) {
    asm volatile("red.global.add.v4.f32 [%0], {%1,%2,%3,%4};"
                 :: "l"(p), "f"(v.x), "f"(v.y), "f"(v.z), "f"(v.w) : "memory");
}

// PAIR-scoped staging: the two warps sharing wN stage W rows [wN*32, wN*32+32)
__device__ __forceinline__ void stage_w_pair(SM* sm, int buf,
    const __half* __restrict__ gw, int K, int k0)
{
    const int lane = threadIdx.x & 31, wid = threadIdx.x >> 5;
    const int wM = wid >> 2, wN = wid & 3;
    const int t = wM * 32 + lane;          // 0..63 within pair
    u32 d = cvta(&sm->W[buf][0]);
#pragma unroll
    for (int i = 0; i < 4; i++) {
        int idx = t + i * 64;              // 0..255 ; 8 cp16 per row
        int r = wN * 32 + (idx >> 3);
        int s = (idx & 7) << 3;
        cpasync16(d + (u32)((r * SW + s) * 2), gw + (size_t)r * K + k0 + s);
    }
}

// GEMM: C[96 x 128] += A(fp16 smem, cols [aCol,aCol+K)) x W^T(fp16, pair-staged)
// 8 warps, warp tile 48x32. Caller staged+committed chunk0 into buf0.
// nBS: leading chunks using BLOCK sync (cross-thread A visibility); rest pair bar.
// firstWait=1: allow ONE trailing pending group at chunk0 (prologue G2).
__device__ __forceinline__ void run_gemm(SM* sm, int aCol, int K,
    const __half* __restrict__ gw, float C[3][4][4], int firstWait, int nBS)
{
    const int tid = threadIdx.x, lane = tid & 31, wid = tid >> 5;
    const int wM = wid >> 2, wN = wid & 3;
#pragma unroll
    for (int i = 0; i < 3; i++)
#pragma unroll
        for (int j = 0; j < 4; j++)
#pragma unroll
            for (int q = 0; q < 4; q++) C[i][j][q] = 0.f;

    const u32 ah_base = cvta(sm->Ah);
    const u32 w_base[2] = { cvta(&sm->W[0][0]), cvta(&sm->W[1][0]) };

    const int aRow0 = wM * 48 + (lane & 15);
    const int aColL = (lane >> 4) * 8;
    const int bRowL = (lane & 7) + ((lane & 16) >> 1);
    const int bColL = lane & 8;

    const int nchunk = K >> 6;
    for (int c = 0; c < nchunk; c++) {
        if (c == 0 && firstWait) cp_wait1(); else cp_wait0();
        if (c < nBS) __syncthreads(); else pair_bar(wN);
        if (c + 1 < nchunk) {
            stage_w_pair(sm, (c + 1) & 1, gw, K, (c + 1) << 6);
            cp_commit();
        }
        const int buf = c & 1, k0 = c << 6;
#pragma unroll
        for (int kk = 0; kk < 64; kk += 16) {
            u32 a_h[3][4];
#pragma unroll
            for (int mi = 0; mi < 3; mi++) {
                u32 off = (u32)(((aRow0 + mi * 16) * SA + aCol + k0 + kk + aColL) * 2);
                ldsm4(ah_base + off, a_h[mi][0], a_h[mi][1], a_h[mi][2], a_h[mi][3]);
            }
            u32 b[4][2];
#pragma unroll
            for (int pr = 0; pr < 2; pr++) {
                u32 off = (u32)(((wN * 32 + pr * 16 + bRowL) * SW + kk + bColL) * 2);
                ldsm4(w_base[buf] + off, b[2*pr][0], b[2*pr][1], b[2*pr+1][0], b[2*pr+1][1]);
            }
#pragma unroll
            for (int mi = 0; mi < 3; mi++)
#pragma unroll
                for (int nb = 0; nb < 4; nb++)
                    mma16816(C[mi][nb], a_h[mi], b[nb]);
        }
    }
}

// fragment owner: rows r=wM*48+mi*16+(lane>>2), r+8 ; cols c=wN*32+nb*8+(lane&3)*2
// hidden = relu(C+b1) fp16 -> Ah cols [256,384)
__device__ __forceinline__ void hidden_epilogue(SM* sm, float C[3][4][4]) {
    const int lane = threadIdx.x & 31, wid = threadIdx.x >> 5;
    const int wM = wid >> 2, wN = wid & 3, g = lane >> 2, q = (lane & 3) * 2;
#pragma unroll
    for (int mi = 0; mi < 3; mi++)
#pragma unroll
        for (int nb = 0; nb < 4; nb++) {
            int r = wM * 48 + mi * 16 + g, c = wN * 32 + nb * 8 + q;
            float b0 = sm->b1[c], b1v = sm->b1[c + 1];
            __half2 t0, t1;
            t0.x = __float2half_rn(fmaxf(C[mi][nb][0] + b0, 0.f));
            t0.y = __float2half_rn(fmaxf(C[mi][nb][1] + b1v, 0.f));
            t1.x = __float2half_rn(fmaxf(C[mi][nb][2] + b0, 0.f));
            t1.y = __float2half_rn(fmaxf(C[mi][nb][3] + b1v, 0.f));
            *(__half2*)&sm->Ah[r * SA + 256 + c] = t0;
            *(__half2*)&sm->Ah[(r + 8) * SA + 256 + c] = t1;
        }
}

// stage C (+bias) as fp32 into Ah per-row bytes [0,512) — disjoint from the last
// GEMM's A reads at half-cols [256,384) = bytes [512,768).
__device__ __forceinline__ void stage_c_f32(SM* sm, float C[3][4][4]) {
    const int lane = threadIdx.x & 31, wid = threadIdx.x >> 5;
    const int wM = wid >> 2, wN = wid & 3, g = lane >> 2, q = (lane & 3) * 2;
#pragma unroll
    for (int mi = 0; mi < 3; mi++)
#pragma unroll
        for (int nb = 0; nb < 4; nb++) {
            int r = wM * 48 + mi * 16 + g, c = wN * 32 + nb * 8 + q;
            float b0 = sm->b2[c], b1v = sm->b2[c + 1];
            float* p0 = (float*)((char*)sm->Ah + (size_t)r * (SA * 2));
            float* p1 = (float*)((char*)sm->Ah + (size_t)(r + 8) * (SA * 2));
            *(float2*)&p0[c] = make_float2(C[mi][nb][0] + b0, C[mi][nb][1] + b1v);
            *(float2*)&p1[c] = make_float2(C[mi][nb][2] + b0, C[mi][nb][3] + b1v);
        }
}

__device__ __forceinline__ void scatter_v4(SM* sm, float C[3][4][4],
                                           float* __restrict__ dst, int rem)
{
    stage_c_f32(sm, C);
    __syncthreads();
    for (int i = threadIdx.x; i < rem * 32; i += NTH) {
        int e = i >> 5, s = (i & 31) * 4;
        const float* rp = (const float*)((char*)sm->Ah + (size_t)e * (SA * 2));
        float4 v = *(const float4*)&rp[s];
        red4(dst + (size_t)sm->colI[e] * 128 + s, v);
    }
}

// ---- fused prep: weights->fp16T, zero x1/x2out, cvt x, cvt ea ----
__global__ void prep_all(const float* __restrict__ w0, const float* __restrict__ w1,
                         const float* __restrict__ w2, const float* __restrict__ w3,
                         const float* __restrict__ w4, const float* __restrict__ w5,
                         const float* __restrict__ w6, const float* __restrict__ w7,
                         __half* __restrict__ dw, float* __restrict__ x2out,
                         const float* __restrict__ x, const float* __restrict__ ea)
{
    const size_t gtid = (size_t)blockIdx.x * blockDim.x + threadIdx.x;
    const size_t gstride = (size_t)gridDim.x * blockDim.x;

    for (size_t idx = gtid; idx < 229376; idx += gstride) {
        const int offs[9] = {0, 49152, 65536, 98304, 114688, 147456, 163840, 212992, 229376};
        const int Ks[8]   = {384, 128, 256, 128, 256, 128, 384, 128};
        const float* ws[8] = {w0, w1, w2, w3, w4, w5, w6, w7};
        int m = 0;
        while ((int)idx >= offs[m + 1]) m++;
        int local = (int)idx - offs[m];
        int K = Ks[m];
        int n = local / K;
        int k = local - n * K;
        dw[idx] = __float2half_rn(ws[m][(size_t)k * 128 + n]);
    }
    for (size_t i = gtid; i < (size_t)NN * 128; i += gstride) {
        g_x1[i] = 0.f;
        x2out[i] = 0.f;
    }
    for (size_t i = gtid; i < (size_t)NN * 32; i += gstride) {
        float4 v = ((const float4*)x)[i];
        __half2 a, b;
        a.x = __float2half_rn(v.x); a.y = __float2half_rn(v.y);
        b.x = __float2half_rn(v.z); b.y = __float2half_rn(v.w);
        ((__half2*)g_x)[i*2] = a; ((__half2*)g_x)[i*2+1] = b;
    }
    for (size_t i = gtid; i < (size_t)NE * 32; i += gstride) {
        float4 v = ((const float4*)ea)[i];
        __half2 a, b;
        a.x = __float2half_rn(v.x); a.y = __float2half_rn(v.y);
        b.x = __float2half_rn(v.z); b.y = __float2half_rn(v.w);
        ((__half2*)g_e1)[i*2] = a; ((__half2*)g_e1)[i*2+1] = b;
    }
}

__global__ void prep_cvt(const float* __restrict__ src, __half* __restrict__ dh, size_t n4)
{
    for (size_t i = (size_t)blockIdx.x * blockDim.x + threadIdx.x; i < n4;
         i += (size_t)gridDim.x * blockDim.x) {
        float4 v = ((const float4*)src)[i];
        __half2 a, b;
        a.x = __float2half_rn(v.x); a.y = __float2half_rn(v.y);
        b.x = __float2half_rn(v.z); b.y = __float2half_rn(v.w);
        ((__half2*)dh)[i*2] = a; ((__half2*)dh)[i*2+1] = b;
    }
}

__device__ __forceinline__ void gather_idx(SM* sm, int seg,
    const __half* __restrict__ src, const int* idx)
{
    u32 ah = cvta(sm->Ah);
    for (int i = threadIdx.x; i < TILE * 16; i += NTH) {
        int e = i >> 4, s = (i & 15) * 8;
        size_t r = (size_t)idx[e];
        cpasync16(ah + (u32)((e * SA + seg + s) * 2), src + r * 128 + s);
    }
}
__device__ __forceinline__ void gather_edge(SM* sm, int seg,
    const __half* __restrict__ src, int e0)
{
    u32 ah = cvta(sm->Ah);
    for (int i = threadIdx.x; i < TILE * 16; i += NTH) {
        int e = i >> 4, s = (i & 15) * 8;
        size_t r = (size_t)min(e0 + e, NE - 1);
        cpasync16(ah + (u32)((e * SA + seg + s) * 2), src + r * 128 + s);
    }
}

__device__ __forceinline__ void load_idx(SM* sm, const int* row, const int* col, int e0)
{
    const int tid = threadIdx.x;
    if (tid < TILE)
        sm->rowI[tid] = (e0 + tid < NE) ? row[e0 + tid] : 0;
    else if (tid < 2 * TILE)
        sm->colI[tid - TILE] = (e0 + tid - TILE < NE) ? col[e0 + tid - TILE] : 0;
}

// ---- Phase A ----
__global__ void __launch_bounds__(NTH, 1)
phaseA(const int* __restrict__ row, const int* __restrict__ col,
       const float* __restrict__ e1b1, const float* __restrict__ e1b2,
       const float* __restrict__ n1b1, const float* __restrict__ n1b2)
{
    extern __shared__ char raw[];
    SM* sm = (SM*)raw;
    const int tid = threadIdx.x;
    const int e0 = blockIdx.x * TILE;
    const int rem = min(TILE, NE - e0);

    load_idx(sm, row, col, e0);
    __syncthreads();

    stage_w_pair(sm, 0, g_w + W_E1W1, 384, 0);
    gather_idx(sm, 0, g_x, sm->rowI);
    cp_commit();                                  // G1: W chunk0 + seg0
    gather_idx(sm, 128, g_x, sm->colI);
    gather_edge(sm, 256, g_e1, e0);               // ea pre-phase-A
    cp_commit();                                  // G2: rest
    if (tid < 128) sm->b1[tid] = e1b1[tid];

    float C[3][4][4];
    run_gemm(sm, 0, 384, g_w + W_E1W1, C, 1, 2);  // 6 chunks; c0,c1 block-sync
    stage_w_pair(sm, 0, g_w + W_E1W2, 128, 0);    // hoisted: buf0 free (ends on buf1)
    cp_commit();
    __syncthreads();                              // all warps done reading A[256,384)
    hidden_epilogue(sm, C);
    if (tid < 128) sm->b2[tid] = e1b2[tid];
    run_gemm(sm, 256, 128, g_w + W_E1W2, C, 0, 1); // c0 block-sync (hidden visibility)
    stage_w_pair(sm, 0, g_w + W_N1W1, 256, 0);    // hoisted (ends on buf1)
    cp_commit();
    {   // e1 (fp16) -> smem cols [128,256)  (disjoint from L2 reads [256,384))
        const int lane = tid & 31, wid = tid >> 5;
        const int wM = wid >> 2, wN = wid & 3, g = lane >> 2, q = (lane & 3) * 2;
#pragma unroll
        for (int mi = 0; mi < 3; mi++)
#pragma unroll
            for (int nb = 0; nb < 4; nb++) {
                int r = wM * 48 + mi * 16 + g, c = wN * 32 + nb * 8 + q;
                float b0 = sm->b2[c], b1v = sm->b2[c + 1];
                __half2 t0, t1;
                t0.x = __float2half_rn(C[mi][nb][0] + b0);
                t0.y = __float2half_rn(C[mi][nb][1] + b1v);
                t1.x = __float2half_rn(C[mi][nb][2] + b0);
                t1.y = __float2half_rn(C[mi][nb][3] + b1v);
                *(__half2*)&sm->Ah[r * SA + 128 + c] = t0;
                *(__half2*)&sm->Ah[(r + 8) * SA + 128 + c] = t1;
            }
    }
    if (tid < 128) sm->b1[tid] = n1b1[tid];
    __syncthreads();
    for (int i = tid; i < TILE * 16; i += NTH) {
        int e = i >> 4, s = (i & 15) * 8;
        if (e < rem)
            *(uint4*)&g_e1[(size_t)(e0 + e) * 128 + s] = *(const uint4*)&sm->Ah[e * SA + 128 + s];
    }
    // MLP2: input cols [0,256) = [x[row], e1] ; A visible via sync above
    run_gemm(sm, 0, 256, g_w + W_N1W1, C, 0, 0);
    stage_w_pair(sm, 0, g_w + W_N1W2, 128, 0);    // hoisted (ends on buf1)
    cp_commit();
    hidden_epilogue(sm, C);                        // [256,384) disjoint from reads [0,256)
    if (tid < 128) sm->b2[tid] = n1b2[tid];
    run_gemm(sm, 256, 128, g_w + W_N1W2, C, 0, 1);
    scatter_v4(sm, C, g_x1, rem);
}

// ---- Phase B ----
__global__ void __launch_bounds__(NTH, 1)
phaseB(const int* __restrict__ row, const int* __restrict__ col,
       const float* __restrict__ n2b1, const float* __restrict__ n2b2,
       float* __restrict__ x2out)
{
    extern __shared__ char raw[];
    SM* sm = (SM*)raw;
    const int tid = threadIdx.x;
    const int e0 = blockIdx.x * TILE;
    const int rem = min(TILE, NE - e0);

    load_idx(sm, row, col, e0);
    __syncthreads();

    stage_w_pair(sm, 0, g_w + W_N2W1, 256, 0);
    gather_idx(sm, 0, g_x1f, sm->rowI);
    cp_commit();                                  // G1
    gather_edge(sm, 128, g_e1, e0);
    cp_commit();                                  // G2
    if (tid < 128) sm->b1[tid] = n2b1[tid];

    float C[3][4][4];
    run_gemm(sm, 0, 256, g_w + W_N2W1, C, 1, 2);  // c0,c1 block-sync
    stage_w_pair(sm, 0, g_w + W_N2W2, 128, 0);    // hoisted (ends on buf1)
    cp_commit();
    hidden_epilogue(sm, C);                        // [256,384) disjoint from reads [0,256)
    if (tid < 128) sm->b2[tid] = n2b2[tid];
    run_gemm(sm, 256, 128, g_w + W_N2W2, C, 0, 1);
    scatter_v4(sm, C, x2out, rem);
}

// ---- Phase C ----
__global__ void __launch_bounds__(NTH, 1)
phaseC(const int* __restrict__ row, const int* __restrict__ col,
       const float* __restrict__ e2b1, const float* __restrict__ e2b2,
       float* __restrict__ e2out)
{
    extern __shared__ char raw[];
    SM* sm = (SM*)raw;
    const int tid = threadIdx.x;
    const int e0 = blockIdx.x * TILE;
    const int rem = min(TILE, NE - e0);

    load_idx(sm, row, col, e0);
    __syncthreads();

    stage_w_pair(sm, 0, g_w + W_E2W1, 384, 0);
    gather_idx(sm, 0, g_x2f, sm->rowI);
    cp_commit();                                  // G1
    gather_idx(sm, 128, g_x2f, sm->colI);
    gather_edge(sm, 256, g_e1, e0);
    cp_commit();                                  // G2
    if (tid < 128) sm->b1[tid] = e2b1[tid];

    float C[3][4][4];
    run_gemm(sm, 0, 384, g_w + W_E2W1, C, 1, 2);  // c0,c1 block-sync
    stage_w_pair(sm, 0, g_w + W_E2W2, 128, 0);    // hoisted (ends on buf1)
    cp_commit();
    __syncthreads();
    hidden_epilogue(sm, C);
    if (tid < 128) sm->b2[tid] = e2b2[tid];
    run_gemm(sm, 256, 128, g_w + W_E2W2, C, 0, 1);

    // e2 direct: stage fp32 (bytes [0,512) disjoint from reads), then store
    stage_c_f32(sm, C);
    __syncthreads();
    for (int i = tid; i < TILE * 32; i += NTH) {
        int e = i >> 5, s = (i & 31) * 4;
        if (e < rem) {
            const float* rp = (const float*)((char*)sm->Ah + (size_t)e * (SA * 2));
            *(float4*)&e2out[(size_t)(e0 + e) * 128 + s] = *(const float4*)&rp[s];
        }
    }
}

extern "C" void kernel_launch(void* const* d_in, const int* in_sizes, int n_in,
                              void* d_out, int out_size)
{
    const float* x    = (const float*)d_in[0];
    const float* ea   = (const float*)d_in[1];
    const int*   ei   = (const int*)d_in[2];
    const float* e1w1 = (const float*)d_in[3];
    const float* e1b1 = (const float*)d_in[4];
    const float* e1w2 = (const float*)d_in[5];
    const float* e1b2 = (const float*)d_in[6];
    const float* n1w1 = (const float*)d_in[7];
    const float* n1b1 = (const float*)d_in[8];
    const float* n1w2 = (const float*)d_in[9];
    const float* n1b2 = (const float*)d_in[10];
    const float* n2w1 = (const float*)d_in[11];
    const float* n2b1 = (const float*)d_in[12];
    const float* n2w2 = (const float*)d_in[13];
    const float* n2b2 = (const float*)d_in[14];
    const float* e2w1 = (const float*)d_in[15];
    const float* e2b1 = (const float*)d_in[16];
    const float* e2w2 = (const float*)d_in[17];
    const float* e2b2 = (const float*)d_in[18];

    const int* row = ei;
    const int* col = ei + NE;

    float* out = (float*)d_out;
    float* x2  = out;
    float* e2o = out + (size_t)NN * 128;

    __half *w, *x1f, *x2f;
    float* x1p;
    cudaGetSymbolAddress((void**)&w, g_w);
    cudaGetSymbolAddress((void**)&x1f, g_x1f);
    cudaGetSymbolAddress((void**)&x2f, g_x2f);
    cudaGetSymbolAddress((void**)&x1p, g_x1);

    prep_all<<<2048, 256>>>(e1w1, e1w2, n1w1, n1w2, n2w1, n2w2, e2w1, e2w2,
                            w, x2, x, ea);

    int smemBytes = (int)sizeof(SM);
    cudaFuncSetAttribute(phaseA, cudaFuncAttributeMaxDynamicSharedMemorySize, smemBytes);
    cudaFuncSetAttribute(phaseB, cudaFuncAttributeMaxDynamicSharedMemorySize, smemBytes);
    cudaFuncSetAttribute(phaseC, cudaFuncAttributeMaxDynamicSharedMemorySize, smemBytes);

    phaseA<<<NBLK, NTH, smemBytes>>>(row, col, e1b1, e1b2, n1b1, n1b2);
    prep_cvt<<<512, 256>>>(x1p, x1f, (size_t)NN * 32);
    phaseB<<<NBLK, NTH, smemBytes>>>(row, col, n2b1, n2b2, x2);
    prep_cvt<<<512, 256>>>(x2, x2f, (size_t)NN * 32);
    phaseC<<<NBLK, NTH, smemBytes>>>(row, col, e2b1, e2b2, e2o);
}

// round 17
// speedup vs baseline: 2.7410x; 1.2846x over previous
#include <cuda_runtime.h>
#include <cuda_fp16.h>
#include <cstdint>

#define NN 40000
#define NE 640000
#define TILE 96
#define NTH 256
#define NBLK ((NE + TILE - 1) / TILE)   // 6667 (last tile: 64 edges)
#define SA 392   // A-plane smem stride (halves)
#define SW 72    // W-plane smem stride (halves)

typedef unsigned int u32;

// ---- device scratch (single fp16 plane activations) ----
__device__ __half g_e1[(size_t)NE * 128];    // ea before phase A, e1 after
__device__ float  g_x1[(size_t)NN * 128];
__device__ __half g_x[(size_t)NN * 128];
__device__ __half g_x1f[(size_t)NN * 128];
__device__ __half g_x2f[(size_t)NN * 128];
__device__ __half g_w[229376];               // fp16, transposed [n][k]

#define W_E1W1 0
#define W_E1W2 49152
#define W_N1W1 65536
#define W_N1W2 98304
#define W_N2W1 114688
#define W_N2W2 147456
#define W_E2W1 163840
#define W_E2W2 212992

struct SM {
    __half Ah[TILE * SA];     // 75264 B ; per-row bytes [0,512) double as fp32 staging
    __half W[2][128 * SW];    // 36864 B
    float b1[128];
    float b2[128];
    int rowI[TILE];
    int colI[TILE];
};                            // ~111.2 KB -> 2 blocks/SM

// ---- helpers ----
__device__ __forceinline__ u32 cvta(const void* p) {
    return (u32)__cvta_generic_to_shared(p);
}
__device__ __forceinline__ void cpasync16(u32 dst, const void* src) {
    asm volatile("cp.async.cg.shared.global [%0], [%1], 16;" :: "r"(dst), "l"(src) : "memory");
}
__device__ __forceinline__ void cp_commit() {
    asm volatile("cp.async.commit_group;" ::: "memory");
}
__device__ __forceinline__ void cp_wait0() {
    asm volatile("cp.async.wait_group 0;" ::: "memory");
}
__device__ __forceinline__ void cp_wait1() {
    asm volatile("cp.async.wait_group 1;" ::: "memory");
}
__device__ __forceinline__ void pair_bar(int wN) {
    asm volatile("bar.sync %0, 64;" :: "r"(1 + wN) : "memory");
}
__device__ __forceinline__ void ldsm4(u32 addr, u32& r0, u32& r1, u32& r2, u32& r3) {
    asm volatile("ldmatrix.sync.aligned.m8n8.x4.shared.b16 {%0,%1,%2,%3}, [%4];"
                 : "=r"(r0), "=r"(r1), "=r"(r2), "=r"(r3) : "r"(addr));
}
__device__ __forceinline__ void mma16816(float* c, const u32* a, const u32* b) {
    asm volatile("mma.sync.aligned.m16n8k16.row.col.f32.f16.f16.f32 "
                 "{%0,%1,%2,%3}, {%4,%5,%6,%7}, {%8,%9}, {%0,%1,%2,%3};"
                 : "+f"(c[0]), "+f"(c[1]), "+f"(c[2]), "+f"(c[3])
                 : "r"(a[0]), "r"(a[1]), "r"(a[2]), "r"(a[3]), "r"(b[0]), "r"(b[1]));
}
__device__ __forceinline__ void red4(float* p, float4 v) {
    asm volatile("red.global.add.v4.f32 [%0], {%1,%2,%3,%4};"
                 :: "l"(p), "f"(v.x), "f"(v.y), "f"(v.z), "f"(v.w) : "memory");
}

// PAIR-scoped staging: the two warps sharing wN stage W rows [wN*32, wN*32+32)
__device__ __forceinline__ void stage_w_pair(SM* sm, int buf,
    const __half* __restrict__ gw, int K, int k0)
{
    const int lane = threadIdx.x & 31, wid = threadIdx.x >> 5;
    const int wM = wid >> 2, wN = wid & 3;
    const int t = wM * 32 + lane;          // 0..63 within pair
    u32 d = cvta(&sm->W[buf][0]);
#pragma unroll
    for (int i = 0; i < 4; i++) {
        int idx = t + i * 64;              // 0..255 ; 8 cp16 per row
        int r = wN * 32 + (idx >> 3);
        int s = (idx & 7) << 3;
        cpasync16(d + (u32)((r * SW + s) * 2), gw + (size_t)r * K + k0 + s);
    }
}

// GEMM: C[96 x 128] += A(fp16 smem, cols [aCol,aCol+K)) x W^T(fp16, pair-staged)
// 8 warps, warp tile 48x32. Caller staged+committed chunk0 into buf0.
// nBS: leading chunks using BLOCK sync; rest pair bar.
// firstWait=1: allow ONE trailing pending group at chunk0 (prologue G2).
__device__ __forceinline__ void run_gemm(SM* sm, int aCol, int K,
    const __half* __restrict__ gw, float C[3][4][4], int firstWait, int nBS)
{
    const int tid = threadIdx.x, lane = tid & 31, wid = tid >> 5;
    const int wM = wid >> 2, wN = wid & 3;
#pragma unroll
    for (int i = 0; i < 3; i++)
#pragma unroll
        for (int j = 0; j < 4; j++)
#pragma unroll
            for (int q = 0; q < 4; q++) C[i][j][q] = 0.f;

    const u32 ah_base = cvta(sm->Ah);
    const u32 w_base[2] = { cvta(&sm->W[0][0]), cvta(&sm->W[1][0]) };

    const int aRow0 = wM * 48 + (lane & 15);
    const int aColL = (lane >> 4) * 8;
    const int bRowL = (lane & 7) + ((lane & 16) >> 1);
    const int bColL = lane & 8;

    const int nchunk = K >> 6;
    for (int c = 0; c < nchunk; c++) {
        if (c == 0 && firstWait) cp_wait1(); else cp_wait0();
        if (c < nBS) __syncthreads(); else pair_bar(wN);
        if (c + 1 < nchunk) {
            stage_w_pair(sm, (c + 1) & 1, gw, K, (c + 1) << 6);
            cp_commit();
        }
        const int buf = c & 1, k0 = c << 6;
#pragma unroll
        for (int kk = 0; kk < 64; kk += 16) {
            u32 a_h[3][4];
#pragma unroll
            for (int mi = 0; mi < 3; mi++) {
                u32 off = (u32)(((aRow0 + mi * 16) * SA + aCol + k0 + kk + aColL) * 2);
                ldsm4(ah_base + off, a_h[mi][0], a_h[mi][1], a_h[mi][2], a_h[mi][3]);
            }
            u32 b[4][2];
#pragma unroll
            for (int pr = 0; pr < 2; pr++) {
                u32 off = (u32)(((wN * 32 + pr * 16 + bRowL) * SW + kk + bColL) * 2);
                ldsm4(w_base[buf] + off, b[2*pr][0], b[2*pr][1], b[2*pr+1][0], b[2*pr+1][1]);
            }
#pragma unroll
            for (int mi = 0; mi < 3; mi++)
#pragma unroll
                for (int nb = 0; nb < 4; nb++)
                    mma16816(C[mi][nb], a_h[mi], b[nb]);
        }
    }
}

// fragment owner: rows r=wM*48+mi*16+(lane>>2), r+8 ; cols c=wN*32+nb*8+(lane&3)*2
__device__ __forceinline__ void hidden_epilogue(SM* sm, float C[3][4][4]) {
    const int lane = threadIdx.x & 31, wid = threadIdx.x >> 5;
    const int wM = wid >> 2, wN = wid & 3, g = lane >> 2, q = (lane & 3) * 2;
#pragma unroll
    for (int mi = 0; mi < 3; mi++)
#pragma unroll
        for (int nb = 0; nb < 4; nb++) {
            int r = wM * 48 + mi * 16 + g, c = wN * 32 + nb * 8 + q;
            float b0 = sm->b1[c], b1v = sm->b1[c + 1];
            __half2 t0, t1;
            t0.x = __float2half_rn(fmaxf(C[mi][nb][0] + b0, 0.f));
            t0.y = __float2half_rn(fmaxf(C[mi][nb][1] + b1v, 0.f));
            t1.x = __float2half_rn(fmaxf(C[mi][nb][2] + b0, 0.f));
            t1.y = __float2half_rn(fmaxf(C[mi][nb][3] + b1v, 0.f));
            *(__half2*)&sm->Ah[r * SA + 256 + c] = t0;
            *(__half2*)&sm->Ah[(r + 8) * SA + 256 + c] = t1;
        }
}

__device__ __forceinline__ void stage_c_f32(SM* sm, float C[3][4][4]) {
    const int lane = threadIdx.x & 31, wid = threadIdx.x >> 5;
    const int wM = wid >> 2, wN = wid & 3, g = lane >> 2, q = (lane & 3) * 2;
#pragma unroll
    for (int mi = 0; mi < 3; mi++)
#pragma unroll
        for (int nb = 0; nb < 4; nb++) {
            int r = wM * 48 + mi * 16 + g, c = wN * 32 + nb * 8 + q;
            float b0 = sm->b2[c], b1v = sm->b2[c + 1];
            float* p0 = (float*)((char*)sm->Ah + (size_t)r * (SA * 2));
            float* p1 = (float*)((char*)sm->Ah + (size_t)(r + 8) * (SA * 2));
            *(float2*)&p0[c] = make_float2(C[mi][nb][0] + b0, C[mi][nb][1] + b1v);
            *(float2*)&p1[c] = make_float2(C[mi][nb][2] + b0, C[mi][nb][3] + b1v);
        }
}

__device__ __forceinline__ void scatter_v4(SM* sm, float C[3][4][4],
                                           float* __restrict__ dst, int rem)
{
    stage_c_f32(sm, C);
    __syncthreads();
    for (int i = threadIdx.x; i < rem * 32; i += NTH) {
        int e = i >> 5, s = (i & 31) * 4;
        const float* rp = (const float*)((char*)sm->Ah + (size_t)e * (SA * 2));
        float4 v = *(const float4*)&rp[s];
        red4(dst + (size_t)sm->colI[e] * 128 + s, v);
    }
}

// ---- fused prep ----
__global__ void prep_all(const float* __restrict__ w0, const float* __restrict__ w1,
                         const float* __restrict__ w2, const float* __restrict__ w3,
                         const float* __restrict__ w4, const float* __restrict__ w5,
                         const float* __restrict__ w6, const float* __restrict__ w7,
                         __half* __restrict__ dw, float* __restrict__ x2out,
                         const float* __restrict__ x, const float* __restrict__ ea)
{
    const size_t gtid = (size_t)blockIdx.x * blockDim.x + threadIdx.x;
    const size_t gstride = (size_t)gridDim.x * blockDim.x;

    for (size_t idx = gtid; idx < 229376; idx += gstride) {
        const int offs[9] = {0, 49152, 65536, 98304, 114688, 147456, 163840, 212992, 229376};
        const int Ks[8]   = {384, 128, 256, 128, 256, 128, 384, 128};
        const float* ws[8] = {w0, w1, w2, w3, w4, w5, w6, w7};
        int m = 0;
        while ((int)idx >= offs[m + 1]) m++;
        int local = (int)idx - offs[m];
        int K = Ks[m];
        int n = local / K;
        int k = local - n * K;
        dw[idx] = __float2half_rn(ws[m][(size_t)k * 128 + n]);
    }
    for (size_t i = gtid; i < (size_t)NN * 128; i += gstride) {
        g_x1[i] = 0.f;
        x2out[i] = 0.f;
    }
    for (size_t i = gtid; i < (size_t)NN * 32; i += gstride) {
        float4 v = ((const float4*)x)[i];
        __half2 a, b;
        a.x = __float2half_rn(v.x); a.y = __float2half_rn(v.y);
        b.x = __float2half_rn(v.z); b.y = __float2half_rn(v.w);
        ((__half2*)g_x)[i*2] = a; ((__half2*)g_x)[i*2+1] = b;
    }
    for (size_t i = gtid; i < (size_t)NE * 32; i += gstride) {
        float4 v = ((const float4*)ea)[i];
        __half2 a, b;
        a.x = __float2half_rn(v.x); a.y = __float2half_rn(v.y);
        b.x = __float2half_rn(v.z); b.y = __float2half_rn(v.w);
        ((__half2*)g_e1)[i*2] = a; ((__half2*)g_e1)[i*2+1] = b;
    }
}

__global__ void prep_cvt(const float* __restrict__ src, __half* __restrict__ dh, size_t n4)
{
    for (size_t i = (size_t)blockIdx.x * blockDim.x + threadIdx.x; i < n4;
         i += (size_t)gridDim.x * blockDim.x) {
        float4 v = ((const float4*)src)[i];
        __half2 a, b;
        a.x = __float2half_rn(v.x); a.y = __float2half_rn(v.y);
        b.x = __float2half_rn(v.z); b.y = __float2half_rn(v.w);
        ((__half2*)dh)[i*2] = a; ((__half2*)dh)[i*2+1] = b;
    }
}

__device__ __forceinline__ void gather_idx(SM* sm, int seg,
    const __half* __restrict__ src, const int* idx)
{
    u32 ah = cvta(sm->Ah);
    for (int i = threadIdx.x; i < TILE * 16; i += NTH) {
        int e = i >> 4, s = (i & 15) * 8;
        size_t r = (size_t)idx[e];
        cpasync16(ah + (u32)((e * SA + seg + s) * 2), src + r * 128 + s);
    }
}
__device__ __forceinline__ void gather_edge(SM* sm, int seg,
    const __half* __restrict__ src, int e0)
{
    u32 ah = cvta(sm->Ah);
    for (int i = threadIdx.x; i < TILE * 16; i += NTH) {
        int e = i >> 4, s = (i & 15) * 8;
        size_t r = (size_t)min(e0 + e, NE - 1);
        cpasync16(ah + (u32)((e * SA + seg + s) * 2), src + r * 128 + s);
    }
}

__device__ __forceinline__ void load_idx(SM* sm, const int* row, const int* col, int e0)
{
    const int tid = threadIdx.x;
    if (tid < TILE)
        sm->rowI[tid] = (e0 + tid < NE) ? row[e0 + tid] : 0;
    else if (tid < 2 * TILE)
        sm->colI[tid - TILE] = (e0 + tid - TILE < NE) ? col[e0 + tid - TILE] : 0;
}

// ---- Phase A ----
__global__ void __launch_bounds__(NTH, 2)
phaseA(const int* __restrict__ row, const int* __restrict__ col,
       const float* __restrict__ e1b1, const float* __restrict__ e1b2,
       const float* __restrict__ n1b1, const float* __restrict__ n1b2)
{
    extern __shared__ char raw[];
    SM* sm = (SM*)raw;
    const int tid = threadIdx.x;
    const int e0 = blockIdx.x * TILE;
    const int rem = min(TILE, NE - e0);

    load_idx(sm, row, col, e0);
    __syncthreads();

    stage_w_pair(sm, 0, g_w + W_E1W1, 384, 0);
    gather_idx(sm, 0, g_x, sm->rowI);
    cp_commit();                                  // G1: W chunk0 + seg0
    gather_idx(sm, 128, g_x, sm->colI);
    gather_edge(sm, 256, g_e1, e0);               // ea pre-phase-A
    cp_commit();                                  // G2: rest
    if (tid < 128) sm->b1[tid] = e1b1[tid];

    float C[3][4][4];
    run_gemm(sm, 0, 384, g_w + W_E1W1, C, 1, 2);  // 6 chunks; c0,c1 block-sync
    stage_w_pair(sm, 0, g_w + W_E1W2, 128, 0);    // hoisted: buf0 free (ends on buf1)
    cp_commit();
    __syncthreads();                              // all warps done reading A[256,384)
    hidden_epilogue(sm, C);
    if (tid < 128) sm->b2[tid] = e1b2[tid];
    run_gemm(sm, 256, 128, g_w + W_E1W2, C, 0, 1); // c0 block-sync (hidden visibility)
    stage_w_pair(sm, 0, g_w + W_N1W1, 256, 0);    // hoisted (ends on buf1)
    cp_commit();
    {   // e1 (fp16) -> smem cols [128,256)  (disjoint from L2 reads [256,384))
        const int lane = tid & 31, wid = tid >> 5;
        const int wM = wid >> 2, wN = wid & 3, g = lane >> 2, q = (lane & 3) * 2;
#pragma unroll
        for (int mi = 0; mi < 3; mi++)
#pragma unroll
            for (int nb = 0; nb < 4; nb++) {
                int r = wM * 48 + mi * 16 + g, c = wN * 32 + nb * 8 + q;
                float b0 = sm->b2[c], b1v = sm->b2[c + 1];
                __half2 t0, t1;
                t0.x = __float2half_rn(C[mi][nb][0] + b0);
                t0.y = __float2half_rn(C[mi][nb][1] + b1v);
                t1.x = __float2half_rn(C[mi][nb][2] + b0);
                t1.y = __float2half_rn(C[mi][nb][3] + b1v);
                *(__half2*)&sm->Ah[r * SA + 128 + c] = t0;
                *(__half2*)&sm->Ah[(r + 8) * SA + 128 + c] = t1;
            }
    }
    if (tid < 128) sm->b1[tid] = n1b1[tid];
    __syncthreads();
    for (int i = tid; i < TILE * 16; i += NTH) {
        int e = i >> 4, s = (i & 15) * 8;
        if (e < rem)
            *(uint4*)&g_e1[(size_t)(e0 + e) * 128 + s] = *(const uint4*)&sm->Ah[e * SA + 128 + s];
    }
    // MLP2: input cols [0,256) = [x[row], e1]
    run_gemm(sm, 0, 256, g_w + W_N1W1, C, 0, 0);
    stage_w_pair(sm, 0, g_w + W_N1W2, 128, 0);    // hoisted (ends on buf1)
    cp_commit();
    hidden_epilogue(sm, C);                        // [256,384) disjoint from reads [0,256)
    if (tid < 128) sm->b2[tid] = n1b2[tid];
    run_gemm(sm, 256, 128, g_w + W_N1W2, C, 0, 1);
    scatter_v4(sm, C, g_x1, rem);
}

// ---- Phase B ----
__global__ void __launch_bounds__(NTH, 2)
phaseB(const int* __restrict__ row, const int* __restrict__ col,
       const float* __restrict__ n2b1, const float* __restrict__ n2b2,
       float* __restrict__ x2out)
{
    extern __shared__ char raw[];
    SM* sm = (SM*)raw;
    const int tid = threadIdx.x;
    const int e0 = blockIdx.x * TILE;
    const int rem = min(TILE, NE - e0);

    load_idx(sm, row, col, e0);
    __syncthreads();

    stage_w_pair(sm, 0, g_w + W_N2W1, 256, 0);
    gather_idx(sm, 0, g_x1f, sm->rowI);
    cp_commit();                                  // G1
    gather_edge(sm, 128, g_e1, e0);
    cp_commit();                                  // G2
    if (tid < 128) sm->b1[tid] = n2b1[tid];

    float C[3][4][4];
    run_gemm(sm, 0, 256, g_w + W_N2W1, C, 1, 2);  // c0,c1 block-sync
    stage_w_pair(sm, 0, g_w + W_N2W2, 128, 0);    // hoisted (ends on buf1)
    cp_commit();
    hidden_epilogue(sm, C);                        // [256,384) disjoint from reads [0,256)
    if (tid < 128) sm->b2[tid] = n2b2[tid];
    run_gemm(sm, 256, 128, g_w + W_N2W2, C, 0, 1);
    scatter_v4(sm, C, x2out, rem);
}

// ---- Phase C ----
__global__ void __launch_bounds__(NTH, 2)
phaseC(const int* __restrict__ row, const int* __restrict__ col,
       const float* __restrict__ e2b1, const float* __restrict__ e2b2,
       float* __restrict__ e2out)
{
    extern __shared__ char raw[];
    SM* sm = (SM*)raw;
    const int tid = threadIdx.x;
    const int e0 = blockIdx.x * TILE;
    const int rem = min(TILE, NE - e0);

    load_idx(sm, row, col, e0);
    __syncthreads();

    stage_w_pair(sm, 0, g_w + W_E2W1, 384, 0);
    gather_idx(sm, 0, g_x2f, sm->rowI);
    cp_commit();                                  // G1
    gather_idx(sm, 128, g_x2f, sm->colI);
    gather_edge(sm, 256, g_e1, e0);
    cp_commit();                                  // G2
    if (tid < 128) sm->b1[tid] = e2b1[tid];

    float C[3][4][4];
    run_gemm(sm, 0, 384, g_w + W_E2W1, C, 1, 2);  // c0,c1 block-sync
    stage_w_pair(sm, 0, g_w + W_E2W2, 128, 0);    // hoisted (ends on buf1)
    cp_commit();
    __syncthreads();
    hidden_epilogue(sm, C);
    if (tid < 128) sm->b2[tid] = e2b2[tid];
    run_gemm(sm, 256, 128, g_w + W_E2W2, C, 0, 1);

    // e2 direct: stage fp32 (bytes [0,512) disjoint from reads), then store
    stage_c_f32(sm, C);
    __syncthreads();
    for (int i = tid; i < TILE * 32; i += NTH) {
        int e = i >> 5, s = (i & 31) * 4;
        if (e < rem) {
            const float* rp = (const float*)((char*)sm->Ah + (size_t)e * (SA * 2));
            *(float4*)&e2out[(size_t)(e0 + e) * 128 + s] = *(const float4*)&rp[s];
        }
    }
}

extern "C" void kernel_launch(void* const* d_in, const int* in_sizes, int n_in,
                              void* d_out, int out_size)
{
    const float* x    = (const float*)d_in[0];
    const float* ea   = (const float*)d_in[1];
    const int*   ei   = (const int*)d_in[2];
    const float* e1w1 = (const float*)d_in[3];
    const float* e1b1 = (const float*)d_in[4];
    const float* e1w2 = (const float*)d_in[5];
    const float* e1b2 = (const float*)d_in[6];
    const float* n1w1 = (const float*)d_in[7];
    const float* n1b1 = (const float*)d_in[8];
    const float* n1w2 = (const float*)d_in[9];
    const float* n1b2 = (const float*)d_in[10];
    const float* n2w1 = (const float*)d_in[11];
    const float* n2b1 = (const float*)d_in[12];
    const float* n2w2 = (const float*)d_in[13];
    const float* n2b2 = (const float*)d_in[14];
    const float* e2w1 = (const float*)d_in[15];
    const float* e2b1 = (const float*)d_in[16];
    const float* e2w2 = (const float*)d_in[17];
    const float* e2b2 = (const float*)d_in[18];

    const int* row = ei;
    const int* col = ei + NE;

    float* out = (float*)d_out;
    float* x2  = out;
    float* e2o = out + (size_t)NN * 128;

    __half *w, *x1f, *x2f;
    float* x1p;
    cudaGetSymbolAddress((void**)&w, g_w);
    cudaGetSymbolAddress((void**)&x1f, g_x1f);
    cudaGetSymbolAddress((void**)&x2f, g_x2f);
    cudaGetSymbolAddress((void**)&x1p, g_x1);

    prep_all<<<2048, 256>>>(e1w1, e1w2, n1w1, n1w2, n2w1, n2w2, e2w1, e2w2,
                            w, x2, x, ea);

    int smemBytes = (int)sizeof(SM);
    cudaFuncSetAttribute(phaseA, cudaFuncAttributeMaxDynamicSharedMemorySize, smemBytes);
    cudaFuncSetAttribute(phaseB, cudaFuncAttributeMaxDynamicSharedMemorySize, smemBytes);
    cudaFuncSetAttribute(phaseC, cudaFuncAttributeMaxDynamicSharedMemorySize, smemBytes);

    phaseA<<<NBLK, NTH, smemBytes>>>(row, col, e1b1, e1b2, n1b1, n1b2);
    prep_cvt<<<512, 256>>>(x1p, x1f, (size_t)NN * 32);
    phaseB<<<NBLK, NTH, smemBytes>>>(row, col, n2b1, n2b2, x2);
    prep_cvt<<<512, 256>>>(x2, x2f, (size_t)NN * 32);
    phaseC<<<NBLK, NTH, smemBytes>>>(row, col, e2b1, e2b2, e2o);
}